// round 8
// baseline (speedup 1.0000x reference)
#include <cuda_runtime.h>
#include <cuda_bf16.h>
#include <cuda_fp16.h>
#include <math.h>

#define NN 100000
#define EE 1250000
#define ET (NN + EE)          // edges + self loops
#define CC 10
#define NB 391                // ceil(NN/256)

// -------- scratch (no allocations allowed) --------
__device__ __half g_lin[NN * 64];    // fp16 packed features for gathers
__device__ float g_act[NN * 64];     // fp32 aggregated activations
__device__ int   g_deg[NN];
__device__ int   g_rowptr[NN + 1];
__device__ int   g_cursor[NN];
__device__ int   g_csr[ET];
__device__ float g_wcsr[ET];         // per-slot GCN norm (written in csr_fill)
__device__ float g_ev[ET];           // per-slot GAT attention logits
__device__ int   g_bsum[512];
__device__ int   g_bbase[512];
__device__ float g_dinv[NN];
__device__ float g_as[NN];
__device__ float g_ad[NN];
__device__ float g_emb[64];

// ======== f32x2 packed math helpers (sm_103a FFMA2) ========
__device__ __forceinline__ unsigned long long pk2(float a, float b) {
    unsigned long long r;
    asm("mov.b64 %0,{%1,%2};" : "=l"(r) : "f"(a), "f"(b));
    return r;
}
__device__ __forceinline__ void upk2(unsigned long long v, float& a, float& b) {
    asm("mov.b64 {%0,%1},%2;" : "=f"(a), "=f"(b) : "l"(v));
}
__device__ __forceinline__ void ffma2(unsigned long long& d, unsigned long long a,
                                      unsigned long long b) {
    asm("fma.rn.f32x2 %0,%1,%2,%0;" : "+l"(d) : "l"(a), "l"(b));
}

// ======== CSR build ========
__global__ void k_deg_init(int* deg) {
    int i = blockIdx.x * blockDim.x + threadIdx.x;
    if (i < NN) deg[i] = 1;                    // self loop
}
__global__ void k_deg_count(const int* __restrict__ dst, int* deg) {
    int t0 = blockIdx.x * 1024 + threadIdx.x;
#pragma unroll
    for (int j = 0; j < 4; j++) {
        int i = t0 + j * 256;
        if (i < EE) atomicAdd(&deg[dst[i]], 1);
    }
}
__global__ void k_blocksum(const int* __restrict__ deg, int* __restrict__ bsum) {
    __shared__ int s[256];
    int t = threadIdx.x;
    int i = blockIdx.x * 256 + t;
    s[t] = (i < NN) ? deg[i] : 0;
    __syncthreads();
    for (int o = 128; o; o >>= 1) {
        if (t < o) s[t] += s[t + o];
        __syncthreads();
    }
    if (t == 0) bsum[blockIdx.x] = s[0];
}
__global__ void k_scanb(const int* __restrict__ bsum, int* __restrict__ bbase) {
    __shared__ int s[512];
    int t = threadIdx.x;
    int v = (t < NB) ? bsum[t] : 0;
    s[t] = v;
    __syncthreads();
    for (int off = 1; off < 512; off <<= 1) {
        int u = (t >= off) ? s[t - off] : 0;
        __syncthreads();
        s[t] += u;
        __syncthreads();
    }
    if (t < NB) bbase[t] = s[t] - v;
}
__global__ void k_rpfill(const int* __restrict__ deg, const int* __restrict__ bbase,
                         int* __restrict__ rp, int* __restrict__ cur,
                         float* __restrict__ dinv) {
    __shared__ int s[256];
    int t = threadIdx.x;
    int i = blockIdx.x * 256 + t;
    int v = (i < NN) ? deg[i] : 0;
    s[t] = v;
    __syncthreads();
    for (int off = 1; off < 256; off <<= 1) {
        int u = (t >= off) ? s[t - off] : 0;
        __syncthreads();
        s[t] += u;
        __syncthreads();
    }
    if (i < NN) {
        int ex = bbase[blockIdx.x] + s[t] - v;
        rp[i] = ex;
        cur[i] = ex;
        dinv[i] = rsqrtf((float)v);
    }
    if (i == 0) rp[NN] = ET;
}
// fills csr AND the GCN edge weights (dinv ready by now)
__global__ void k_csr_fill(const int* __restrict__ src, const int* __restrict__ dst,
                           int* __restrict__ cur, int* __restrict__ csr,
                           const float* __restrict__ dinv, float* __restrict__ wcsr) {
    int t0 = blockIdx.x * 1024 + threadIdx.x;
#pragma unroll
    for (int j = 0; j < 4; j++) {
        int i = t0 + j * 256;
        if (i < ET) {
            int s, d;
            if (i < EE) { s = src[i]; d = dst[i]; } else { s = d = i - EE; }
            int pos = atomicAdd(&cur[d], 1);
            csr[pos] = s;
            wcsr[pos] = dinv[s] * dinv[d];
        }
    }
}

// ======== GEMM: C_h[M,64] = A[M,K] @ W[K,64] (half output), optional fused alpha ========
template <int K, bool ALPHA>
__global__ void k_gemm2(const float* __restrict__ A, const float* __restrict__ W,
                        __half* __restrict__ C,
                        const float* __restrict__ avs, const float* __restrict__ avd,
                        float* __restrict__ as_out, float* __restrict__ ad_out, int M) {
    extern __shared__ float sm[];
    float* Ws = sm;                 // K*64
    float* Xs = sm + K * 64;        // K*132 (transposed, padded)
    int tid = threadIdx.x;
    for (int idx = tid; idx < K * 64; idx += 256) Ws[idx] = W[idx];
    int base = blockIdx.x * 128;
    for (int idx = tid; idx < 128 * K; idx += 256) {
        int n = idx / K, k = idx - n * K;
        int row = base + n;
        Xs[k * 132 + n] = (row < M) ? A[row * K + k] : 0.f;
    }
    __syncthreads();
    int c0 = (tid & 7) * 8;
    int n0 = (tid >> 3) * 4;
    unsigned long long acc[4][4];
#pragma unroll
    for (int r = 0; r < 4; r++)
#pragma unroll
        for (int c = 0; c < 4; c++) acc[r][c] = 0ull;
#pragma unroll 8
    for (int k = 0; k < K; k++) {
        float4 w0 = *(const float4*)&Ws[k * 64 + c0];
        float4 w1 = *(const float4*)&Ws[k * 64 + c0 + 4];
        float4 xv = *(const float4*)&Xs[k * 132 + n0];
        unsigned long long wp0 = pk2(w0.x, w0.y), wp1 = pk2(w0.z, w0.w);
        unsigned long long wp2 = pk2(w1.x, w1.y), wp3 = pk2(w1.z, w1.w);
        unsigned long long x0 = pk2(xv.x, xv.x), x1 = pk2(xv.y, xv.y);
        unsigned long long x2 = pk2(xv.z, xv.z), x3 = pk2(xv.w, xv.w);
        ffma2(acc[0][0], x0, wp0); ffma2(acc[0][1], x0, wp1);
        ffma2(acc[0][2], x0, wp2); ffma2(acc[0][3], x0, wp3);
        ffma2(acc[1][0], x1, wp0); ffma2(acc[1][1], x1, wp1);
        ffma2(acc[1][2], x1, wp2); ffma2(acc[1][3], x1, wp3);
        ffma2(acc[2][0], x2, wp0); ffma2(acc[2][1], x2, wp1);
        ffma2(acc[2][2], x2, wp2); ffma2(acc[2][3], x2, wp3);
        ffma2(acc[3][0], x3, wp0); ffma2(acc[3][1], x3, wp1);
        ffma2(acc[3][2], x3, wp2); ffma2(acc[3][3], x3, wp3);
    }
    float sav[8], dav[8];
    if (ALPHA) {
#pragma unroll
        for (int j = 0; j < 8; j++) { sav[j] = avs[c0 + j]; dav[j] = avd[c0 + j]; }
    }
#pragma unroll
    for (int r = 0; r < 4; r++) {
        int row = base + n0 + r;
        float f[8];
        upk2(acc[r][0], f[0], f[1]); upk2(acc[r][1], f[2], f[3]);
        upk2(acc[r][2], f[4], f[5]); upk2(acc[r][3], f[6], f[7]);
        if (row < M) {
            __half2 hh[4];
#pragma unroll
            for (int j = 0; j < 4; j++)
                hh[j] = __float22half2_rn(make_float2(f[2 * j], f[2 * j + 1]));
            *(uint4*)&C[row * 64 + c0] = *(uint4*)hh;
        }
        if (ALPHA) {
            float sp = 0.f, dp = 0.f;
#pragma unroll
            for (int j = 0; j < 8; j++) { sp = fmaf(f[j], sav[j], sp); dp = fmaf(f[j], dav[j], dp); }
#pragma unroll
            for (int o = 1; o < 8; o <<= 1) {
                sp += __shfl_xor_sync(0xffffffffu, sp, o);
                dp += __shfl_xor_sync(0xffffffffu, dp, o);
            }
            if ((tid & 7) == 0 && row < M) { as_out[row] = sp; ad_out[row] = dp; }
        }
    }
}

// ======== 8-lane-group gather: lane q holds halves 8q..8q+7 of the row ========
__device__ __forceinline__ void hacc8(const uint4* __restrict__ hp, int s, int q, float m,
                                      float acc[8]) {
    uint4 rv = hp[(unsigned)s * 8 + q];
    float2 f0 = __half22float2(*(__half2*)&rv.x);
    float2 f1 = __half22float2(*(__half2*)&rv.y);
    float2 f2 = __half22float2(*(__half2*)&rv.z);
    float2 f3 = __half22float2(*(__half2*)&rv.w);
    acc[0] = fmaf(f0.x, m, acc[0]); acc[1] = fmaf(f0.y, m, acc[1]);
    acc[2] = fmaf(f1.x, m, acc[2]); acc[3] = fmaf(f1.y, m, acc[3]);
    acc[4] = fmaf(f2.x, m, acc[4]); acc[5] = fmaf(f2.y, m, acc[5]);
    acc[6] = fmaf(f3.x, m, acc[6]); acc[7] = fmaf(f3.y, m, acc[7]);
}

__device__ __forceinline__ void store_act(float acc[8], const float* __restrict__ b,
                                          float* __restrict__ act, int node, int q) {
    int fi = q * 8;
    float4 b0 = *(const float4*)&b[fi];
    float4 b1 = *(const float4*)&b[fi + 4];
    float4 o0 = make_float4(fmaxf(acc[0] + b0.x, 0.f), fmaxf(acc[1] + b0.y, 0.f),
                            fmaxf(acc[2] + b0.z, 0.f), fmaxf(acc[3] + b0.w, 0.f));
    float4 o1 = make_float4(fmaxf(acc[4] + b1.x, 0.f), fmaxf(acc[5] + b1.y, 0.f),
                            fmaxf(acc[6] + b1.z, 0.f), fmaxf(acc[7] + b1.w, 0.f));
    *(float4*)&act[node * 64 + fi]     = o0;
    *(float4*)&act[node * 64 + fi + 4] = o1;
}

// ======== GCN aggregation: 8-lane group per node, no cross-lane reduction ========
__global__ void k_gcn_agg(const __half* __restrict__ h, const int* __restrict__ rp,
                          const int* __restrict__ csr, const float* __restrict__ wcsr,
                          const float* __restrict__ b, float* __restrict__ act) {
    int node = blockIdx.x * 32 + (threadIdx.x >> 3);
    if (node >= NN) return;
    int q = threadIdx.x & 7;
    const uint4* hp = (const uint4*)h;
    int e = rp[node], end = rp[node + 1];
    float acc[8];
#pragma unroll
    for (int j = 0; j < 8; j++) acc[j] = 0.f;
    for (; e + 4 <= end; e += 4) {
        int s0 = csr[e], s1 = csr[e + 1], s2 = csr[e + 2], s3 = csr[e + 3];
        float w0 = wcsr[e], w1 = wcsr[e + 1], w2 = wcsr[e + 2], w3 = wcsr[e + 3];
        hacc8(hp, s0, q, w0, acc);
        hacc8(hp, s1, q, w1, acc);
        hacc8(hp, s2, q, w2, acc);
        hacc8(hp, s3, q, w3, acc);
    }
    for (; e < end; e++) hacc8(hp, csr[e], q, wcsr[e], acc);
    store_act(acc, b, act, node, q);
}

__device__ __forceinline__ float lrelu(float v) { return v >= 0.f ? v : 0.2f * v; }

// ======== fused GAT aggregation: group softmax + ev spill + weighted gather ========
__global__ void k_gat_agg(const __half* __restrict__ h, const int* __restrict__ rp,
                          const int* __restrict__ csr, const float* __restrict__ as_,
                          const float* __restrict__ ad_, float* __restrict__ ev,
                          const float* __restrict__ b, float* __restrict__ act) {
    int node = blockIdx.x * 32 + (threadIdx.x >> 3);
    if (node >= NN) return;
    int q = threadIdx.x & 7;
    const uint4* hp = (const uint4*)h;
    int begin = rp[node], end = rp[node + 1];
    float adv = ad_[node];

    // pass 1: online max+sum over edges (8 lanes strided), spill logits
    float mx = -1e30f, sum = 0.f;
    for (int e = begin + q; e < end; e += 8) {
        float a = lrelu(as_[csr[e]] + adv);
        ev[e] = a;
        float mn = fmaxf(mx, a);
        sum = sum * __expf(mx - mn) + __expf(a - mn);
        mx = mn;
    }
#pragma unroll
    for (int o = 1; o < 8; o <<= 1) {
        float m2 = __shfl_xor_sync(0xffffffffu, mx, o);
        float s2 = __shfl_xor_sync(0xffffffffu, sum, o);
        float mn = fmaxf(mx, m2);
        sum = sum * __expf(mx - mn) + s2 * __expf(m2 - mn);
        mx = mn;
    }
    float inv = 1.f / sum;

    // pass 2: weighted gather, one row per group-instruction
    float acc[8];
#pragma unroll
    for (int j = 0; j < 8; j++) acc[j] = 0.f;
    int e = begin;
    for (; e + 4 <= end; e += 4) {
        int s0 = csr[e], s1 = csr[e + 1], s2 = csr[e + 2], s3 = csr[e + 3];
        float a0 = __expf(ev[e] - mx) * inv;
        float a1 = __expf(ev[e + 1] - mx) * inv;
        float a2 = __expf(ev[e + 2] - mx) * inv;
        float a3 = __expf(ev[e + 3] - mx) * inv;
        hacc8(hp, s0, q, a0, acc);
        hacc8(hp, s1, q, a1, acc);
        hacc8(hp, s2, q, a2, acc);
        hacc8(hp, s3, q, a3, acc);
    }
    for (; e < end; e++) {
        float al = __expf(ev[e] - mx) * inv;
        hacc8(hp, csr[e], q, al, acc);
    }
    store_act(acc, b, act, node, q);
}

// ======== heads + fused graph-embedding partials (Wb1 in registers) ========
__global__ void k_heads(const float* __restrict__ h,
                        const float* __restrict__ Wopt, const float* __restrict__ bopt,
                        const float* __restrict__ Wb1, const float* __restrict__ bb1,
                        const float* __restrict__ Wb2, const float* __restrict__ bb2,
                        float* __restrict__ out, float* __restrict__ emb, int n) {
    __shared__ float sWopt[640], sbopt[10], sbb1[32], sWb2[32];
    __shared__ float hrow[8][64];
    int tid = threadIdx.x;
    for (int i = tid; i < 640; i += 256) sWopt[i] = Wopt[i];
    if (tid < 10) sbopt[tid] = bopt[tid];
    if (tid < 32) { sbb1[tid] = bb1[tid]; sWb2[tid] = Wb2[tid]; }
    __syncthreads();
    float bb2v = bb2[0];
    int warp = tid >> 5, lane = tid & 31;
    float wb1r[64];
#pragma unroll
    for (int k = 0; k < 64; k++) wb1r[k] = Wb1[k * 32 + lane];
    float p0 = 0.f, p1 = 0.f;
    bool opt_lane = lane < CC;
    for (int node = blockIdx.x * 8 + warp; node < n; node += gridDim.x * 8) {
        float h0 = h[node * 64 + lane];
        float h1 = h[node * 64 + 32 + lane];
        hrow[warp][lane] = h0;
        hrow[warp][lane + 32] = h1;
        p0 += h0; p1 += h1;
        __syncwarp();
        float t = sbb1[lane];
        float acc = opt_lane ? sbopt[lane] : 0.f;
#pragma unroll
        for (int k = 0; k < 64; k++) {
            float hk = hrow[warp][k];
            t = fmaf(hk, wb1r[k], t);
            if (opt_lane) acc = fmaf(hk, sWopt[k * CC + lane], acc);
        }
        if (opt_lane) out[node * CC + lane] = acc;
        t = fmaxf(t, 0.f) * sWb2[lane];
#pragma unroll
        for (int o = 16; o; o >>= 1) t += __shfl_down_sync(0xffffffffu, t, o);
        if (lane == 0) out[NN * CC + node] = 1.f / (1.f + __expf(-(t + bb2v)));
        __syncwarp();
    }
    atomicAdd(&emb[lane], p0);
    atomicAdd(&emb[lane + 32], p1);
}

__global__ void k_fill(float* p, float v, int n) {
    int i = blockIdx.x * blockDim.x + threadIdx.x;
    if (i < n) p[i] = v;
}
__global__ void k_finish(const float* __restrict__ emb, float* __restrict__ out) {
    int t = threadIdx.x;
    if (t < 64) out[NN * CC + NN + t] = emb[t] * (1.0f / NN);
}

// ======== launch ========
extern "C" void kernel_launch(void* const* d_in, const int* in_sizes, int n_in,
                              void* d_out, int out_size) {
    const float* x    = (const float*)d_in[0];
    const int*   ei   = (const int*)d_in[1];
    const int*   src  = ei;
    const int*   dst  = ei + EE;
    const float* W1   = (const float*)d_in[2];
    const float* b1   = (const float*)d_in[3];
    const float* W2   = (const float*)d_in[4];
    const float* a_s  = (const float*)d_in[5];
    const float* a_d  = (const float*)d_in[6];
    const float* b2   = (const float*)d_in[7];
    const float* W3   = (const float*)d_in[8];
    const float* b3   = (const float*)d_in[9];
    const float* Wopt = (const float*)d_in[10];
    const float* bopt = (const float*)d_in[11];
    const float* Wb1  = (const float*)d_in[12];
    const float* bb1  = (const float*)d_in[13];
    const float* Wb2  = (const float*)d_in[14];
    const float* bb2  = (const float*)d_in[15];
    float* out = (float*)d_out;

    __half* pLin;
    float *pAct, *pDinv, *pAs, *pAd, *pEmb, *pWcsr, *pEv;
    int *pDeg, *pRp, *pCur, *pCsr, *pBsum, *pBbase;
    cudaGetSymbolAddress((void**)&pLin,  g_lin);
    cudaGetSymbolAddress((void**)&pAct,  g_act);
    cudaGetSymbolAddress((void**)&pDeg,  g_deg);
    cudaGetSymbolAddress((void**)&pRp,   g_rowptr);
    cudaGetSymbolAddress((void**)&pCur,  g_cursor);
    cudaGetSymbolAddress((void**)&pCsr,  g_csr);
    cudaGetSymbolAddress((void**)&pWcsr, g_wcsr);
    cudaGetSymbolAddress((void**)&pEv,   g_ev);
    cudaGetSymbolAddress((void**)&pBsum, g_bsum);
    cudaGetSymbolAddress((void**)&pBbase,g_bbase);
    cudaGetSymbolAddress((void**)&pDinv, g_dinv);
    cudaGetSymbolAddress((void**)&pAs,   g_as);
    cudaGetSymbolAddress((void**)&pAd,   g_ad);
    cudaGetSymbolAddress((void**)&pEmb,  g_emb);

    const int TB = 256;
    const int nBlkA = (NN + 31) / 32;              // 8-lane group per node
    const int nBlkG = (NN + 127) / 128;
    const int smem32 = 32 * (64 + 132) * 4;
    const int smem64 = 64 * (64 + 132) * 4;

    static cudaStream_t s1 = nullptr;
    static cudaEvent_t ev0 = nullptr, ev1 = nullptr;
    static int attr_done = 0;
    if (!attr_done) {
        cudaFuncSetAttribute(k_gemm2<64, true>,  cudaFuncAttributeMaxDynamicSharedMemorySize, smem64);
        cudaFuncSetAttribute(k_gemm2<64, false>, cudaFuncAttributeMaxDynamicSharedMemorySize, smem64);
        cudaFuncSetAttribute(k_gemm2<32, false>, cudaFuncAttributeMaxDynamicSharedMemorySize, smem32);
        cudaStreamCreateWithFlags(&s1, cudaStreamNonBlocking);
        cudaEventCreateWithFlags(&ev0, cudaEventDisableTiming);
        cudaEventCreateWithFlags(&ev1, cudaEventDisableTiming);
        attr_done = 1;
    }

    // ---- fork: CSR build on s1, overlapped with GEMM1 on stream 0 ----
    cudaEventRecord(ev0, 0);
    cudaStreamWaitEvent(s1, ev0, 0);
    k_deg_init<<<NB, TB, 0, s1>>>(pDeg);
    k_deg_count<<<(EE + 1023) / 1024, TB, 0, s1>>>(dst, pDeg);
    k_blocksum<<<NB, TB, 0, s1>>>(pDeg, pBsum);
    k_scanb<<<1, 512, 0, s1>>>(pBsum, pBbase);
    k_rpfill<<<NB, TB, 0, s1>>>(pDeg, pBbase, pRp, pCur, pDinv);
    k_csr_fill<<<(ET + 1023) / 1024, TB, 0, s1>>>(src, dst, pCur, pCsr, pDinv, pWcsr);
    k_fill<<<1, 64, 0, s1>>>(pEmb, 0.f, 64);
    cudaEventRecord(ev1, s1);

    // ---- GCN layer 1 ----
    k_gemm2<32, false><<<nBlkG, TB, smem32>>>(x, W1, pLin, nullptr, nullptr, nullptr, nullptr, NN);
    cudaStreamWaitEvent(0, ev1, 0);   // join: aggs need CSR + weights
    k_gcn_agg<<<nBlkA, TB>>>(pLin, pRp, pCsr, pWcsr, b1, pAct);

    // ---- GAT layer (alpha fused into GEMM epilogue) ----
    k_gemm2<64, true><<<nBlkG, TB, smem64>>>(pAct, W2, pLin, a_s, a_d, pAs, pAd, NN);
    k_gat_agg<<<nBlkA, TB>>>(pLin, pRp, pCsr, pAs, pAd, pEv, b2, pAct);

    // ---- GCN layer 3 ----
    k_gemm2<64, false><<<nBlkG, TB, smem64>>>(pAct, W3, pLin, nullptr, nullptr, nullptr, nullptr, NN);
    k_gcn_agg<<<nBlkA, TB>>>(pLin, pRp, pCsr, pWcsr, b3, pAct);

    // ---- heads + embedding ----
    k_heads<<<1184, TB>>>(pAct, Wopt, bopt, Wb1, bb1, Wb2, bb2, out, pEmb, NN);
    k_finish<<<1, 64>>>(pEmb, out);
}

// round 9
// speedup vs baseline: 1.0289x; 1.0289x over previous
#include <cuda_runtime.h>
#include <cuda_bf16.h>
#include <cuda_fp16.h>
#include <math.h>

#define NN 100000
#define EE 1250000
#define ET (NN + EE)          // edges + self loops
#define CC 10
#define NB 391                // ceil(NN/256)

// -------- scratch (no allocations allowed) --------
__device__ __half g_lin[NN * 64];    // fp16 packed features for gathers
__device__ float g_act[NN * 64];     // fp32 aggregated activations
__device__ int   g_deg[NN];          // starts zero (BSS); re-zeroed by k_rp each launch
__device__ int   g_rowptr[NN];
__device__ int   g_len[NN];
__device__ int   g_cursor[NN];
__device__ int   g_csr[ET];
__device__ float g_wcsr[ET];         // per-slot GCN norm (written in csr_fill)
__device__ float g_ev[ET];           // per-slot GAT exp(logit)
__device__ float g_dinv[NN];
__device__ float g_as[NN];
__device__ float g_ad[NN];
__device__ float g_emb[64];
__device__ int   g_ctr[4];           // [0]=rp base, [1]=rp ticket, [2]=heads ticket

// ======== f32x2 packed math helpers (sm_103a FFMA2) ========
__device__ __forceinline__ unsigned long long pk2(float a, float b) {
    unsigned long long r;
    asm("mov.b64 %0,{%1,%2};" : "=l"(r) : "f"(a), "f"(b));
    return r;
}
__device__ __forceinline__ void upk2(unsigned long long v, float& a, float& b) {
    asm("mov.b64 {%0,%1},%2;" : "=f"(a), "=f"(b) : "l"(v));
}
__device__ __forceinline__ void ffma2(unsigned long long& d, unsigned long long a,
                                      unsigned long long b) {
    asm("fma.rn.f32x2 %0,%1,%2,%0;" : "+l"(d) : "l"(a), "l"(b));
}

// ======== CSR build ========
__global__ void k_deg_count(const int* __restrict__ dst, int* deg) {
    int t0 = blockIdx.x * 1024 + threadIdx.x;
#pragma unroll
    for (int j = 0; j < 4; j++) {
        int i = t0 + j * 256;
        if (i < EE) atomicAdd(&deg[dst[i]], 1);
    }
}
// fused: block scan + atomic base -> rowptr/cursor/len/dinv; zeroes deg + emb; resets ctr
__global__ void k_rp(int* __restrict__ deg, int* __restrict__ rp, int* __restrict__ cur,
                     int* __restrict__ len, float* __restrict__ dinv,
                     float* __restrict__ emb, int* __restrict__ ctr) {
    __shared__ int s[256];
    __shared__ int base;
    int t = threadIdx.x;
    int i = blockIdx.x * 256 + t;
    int v = (i < NN) ? (deg[i] + 1) : 0;       // +1 self loop
    s[t] = v;
    __syncthreads();
    for (int off = 1; off < 256; off <<= 1) {
        int u = (t >= off) ? s[t - off] : 0;
        __syncthreads();
        s[t] += u;
        __syncthreads();
    }
    if (t == 255) base = atomicAdd(&ctr[0], s[255]);
    __syncthreads();
    if (i < NN) {
        int ex = base + s[t] - v;
        rp[i] = ex;
        cur[i] = ex;
        len[i] = v;
        dinv[i] = rsqrtf((float)v);
        deg[i] = 0;                            // ready for next replay
    }
    if (blockIdx.x == 0 && t < 64) emb[t] = 0.f;
    __threadfence();
    if (t == 0) {
        int done = atomicAdd(&ctr[1], 1);
        if (done == gridDim.x - 1) { ctr[0] = 0; ctr[1] = 0; }
    }
}
// fills csr AND the GCN edge weights (dinv ready by now)
__global__ void k_csr_fill(const int* __restrict__ src, const int* __restrict__ dst,
                           int* __restrict__ cur, int* __restrict__ csr,
                           const float* __restrict__ dinv, float* __restrict__ wcsr) {
    int t0 = blockIdx.x * 1024 + threadIdx.x;
#pragma unroll
    for (int j = 0; j < 4; j++) {
        int i = t0 + j * 256;
        if (i < ET) {
            int s, d;
            if (i < EE) { s = src[i]; d = dst[i]; } else { s = d = i - EE; }
            int pos = atomicAdd(&cur[d], 1);
            csr[pos] = s;
            wcsr[pos] = dinv[s] * dinv[d];
        }
    }
}

// ======== GEMM: C_h[M,64] = A[M,K] @ W[K,64] (half output), optional fused alpha ========
template <int K, bool ALPHA>
__global__ void k_gemm2(const float* __restrict__ A, const float* __restrict__ W,
                        __half* __restrict__ C,
                        const float* __restrict__ avs, const float* __restrict__ avd,
                        float* __restrict__ as_out, float* __restrict__ ad_out, int M) {
    extern __shared__ float sm[];
    float* Ws = sm;                 // K*64
    float* Xs = sm + K * 64;        // K*132 (transposed, padded)
    int tid = threadIdx.x;
    for (int idx = tid; idx < K * 64; idx += 256) Ws[idx] = W[idx];
    int base = blockIdx.x * 128;
    for (int idx = tid; idx < 128 * K; idx += 256) {
        int n = idx / K, k = idx - n * K;
        int row = base + n;
        Xs[k * 132 + n] = (row < M) ? A[row * K + k] : 0.f;
    }
    __syncthreads();
    int c0 = (tid & 7) * 8;
    int n0 = (tid >> 3) * 4;
    unsigned long long acc[4][4];
#pragma unroll
    for (int r = 0; r < 4; r++)
#pragma unroll
        for (int c = 0; c < 4; c++) acc[r][c] = 0ull;
#pragma unroll 8
    for (int k = 0; k < K; k++) {
        float4 w0 = *(const float4*)&Ws[k * 64 + c0];
        float4 w1 = *(const float4*)&Ws[k * 64 + c0 + 4];
        float4 xv = *(const float4*)&Xs[k * 132 + n0];
        unsigned long long wp0 = pk2(w0.x, w0.y), wp1 = pk2(w0.z, w0.w);
        unsigned long long wp2 = pk2(w1.x, w1.y), wp3 = pk2(w1.z, w1.w);
        unsigned long long x0 = pk2(xv.x, xv.x), x1 = pk2(xv.y, xv.y);
        unsigned long long x2 = pk2(xv.z, xv.z), x3 = pk2(xv.w, xv.w);
        ffma2(acc[0][0], x0, wp0); ffma2(acc[0][1], x0, wp1);
        ffma2(acc[0][2], x0, wp2); ffma2(acc[0][3], x0, wp3);
        ffma2(acc[1][0], x1, wp0); ffma2(acc[1][1], x1, wp1);
        ffma2(acc[1][2], x1, wp2); ffma2(acc[1][3], x1, wp3);
        ffma2(acc[2][0], x2, wp0); ffma2(acc[2][1], x2, wp1);
        ffma2(acc[2][2], x2, wp2); ffma2(acc[2][3], x2, wp3);
        ffma2(acc[3][0], x3, wp0); ffma2(acc[3][1], x3, wp1);
        ffma2(acc[3][2], x3, wp2); ffma2(acc[3][3], x3, wp3);
    }
    float sav[8], dav[8];
    if (ALPHA) {
#pragma unroll
        for (int j = 0; j < 8; j++) { sav[j] = avs[c0 + j]; dav[j] = avd[c0 + j]; }
    }
#pragma unroll
    for (int r = 0; r < 4; r++) {
        int row = base + n0 + r;
        float f[8];
        upk2(acc[r][0], f[0], f[1]); upk2(acc[r][1], f[2], f[3]);
        upk2(acc[r][2], f[4], f[5]); upk2(acc[r][3], f[6], f[7]);
        if (row < M) {
            __half2 hh[4];
#pragma unroll
            for (int j = 0; j < 4; j++)
                hh[j] = __float22half2_rn(make_float2(f[2 * j], f[2 * j + 1]));
            *(uint4*)&C[row * 64 + c0] = *(uint4*)hh;
        }
        if (ALPHA) {
            float sp = 0.f, dp = 0.f;
#pragma unroll
            for (int j = 0; j < 8; j++) { sp = fmaf(f[j], sav[j], sp); dp = fmaf(f[j], dav[j], dp); }
#pragma unroll
            for (int o = 1; o < 8; o <<= 1) {
                sp += __shfl_xor_sync(0xffffffffu, sp, o);
                dp += __shfl_xor_sync(0xffffffffu, dp, o);
            }
            if ((tid & 7) == 0 && row < M) { as_out[row] = sp; ad_out[row] = dp; }
        }
    }
}

// ======== quarter-warp gather: lane q in group holds halves 8q..8q+7 ========
__device__ __forceinline__ void hacc8(const uint4* __restrict__ hp, int s, int q, float m,
                                      float acc[8]) {
    uint4 rv = hp[(unsigned)s * 8 + q];
    float2 f0 = __half22float2(*(__half2*)&rv.x);
    float2 f1 = __half22float2(*(__half2*)&rv.y);
    float2 f2 = __half22float2(*(__half2*)&rv.z);
    float2 f3 = __half22float2(*(__half2*)&rv.w);
    acc[0] = fmaf(f0.x, m, acc[0]); acc[1] = fmaf(f0.y, m, acc[1]);
    acc[2] = fmaf(f1.x, m, acc[2]); acc[3] = fmaf(f1.y, m, acc[3]);
    acc[4] = fmaf(f2.x, m, acc[4]); acc[5] = fmaf(f2.y, m, acc[5]);
    acc[6] = fmaf(f3.x, m, acc[6]); acc[7] = fmaf(f3.y, m, acc[7]);
}

__device__ __forceinline__ void agg_epilogue(float acc[8], const float* __restrict__ b,
                                             float* __restrict__ act, int node, int lane) {
#pragma unroll
    for (int j = 0; j < 8; j++) {
        acc[j] += __shfl_xor_sync(0xffffffffu, acc[j], 8);
        acc[j] += __shfl_xor_sync(0xffffffffu, acc[j], 16);
    }
    if (lane < 8) {
        int fi = lane * 8;
        float4 b0 = *(const float4*)&b[fi];
        float4 b1 = *(const float4*)&b[fi + 4];
        float4 o0 = make_float4(fmaxf(acc[0] + b0.x, 0.f), fmaxf(acc[1] + b0.y, 0.f),
                                fmaxf(acc[2] + b0.z, 0.f), fmaxf(acc[3] + b0.w, 0.f));
        float4 o1 = make_float4(fmaxf(acc[4] + b1.x, 0.f), fmaxf(acc[5] + b1.y, 0.f),
                                fmaxf(acc[6] + b1.z, 0.f), fmaxf(acc[7] + b1.w, 0.f));
        *(float4*)&act[node * 64 + fi]     = o0;
        *(float4*)&act[node * 64 + fi + 4] = o1;
    }
}

// ======== GCN aggregation: warp per node, quarter-warp per edge ========
__global__ void k_gcn_agg(const __half* __restrict__ h, const int* __restrict__ rp,
                          const int* __restrict__ lenv, const int* __restrict__ csr,
                          const float* __restrict__ wcsr,
                          const float* __restrict__ b, float* __restrict__ act) {
    int node = blockIdx.x * 8 + (threadIdx.x >> 5);
    if (node >= NN) return;
    int lane = threadIdx.x & 31;
    int g = lane >> 3;          // quarter id
    int q = lane & 7;           // lane in quarter
    const uint4* hp = (const uint4*)h;
    int e = rp[node];
    int end = e + lenv[node];
    float acc[8];
#pragma unroll
    for (int j = 0; j < 8; j++) acc[j] = 0.f;
    for (; e + 8 <= end; e += 8) {
        int eA = e + g, eB = e + 4 + g;
        int sA = csr[eA], sB = csr[eB];
        float mA = wcsr[eA], mB = wcsr[eB];
        hacc8(hp, sA, q, mA, acc);
        hacc8(hp, sB, q, mB, acc);
    }
    for (; e < end; e += 4) {
        int ee = e + g;
        if (ee < end) hacc8(hp, csr[ee], q, wcsr[ee], acc);
    }
    agg_epilogue(acc, b, act, node, lane);
}

__device__ __forceinline__ float lrelu(float v) { return v >= 0.f ? v : 0.2f * v; }

// ======== fused GAT aggregation: no-max softmax + exp spill + weighted gather ========
__global__ void k_gat_agg(const __half* __restrict__ h, const int* __restrict__ rp,
                          const int* __restrict__ lenv, const int* __restrict__ csr,
                          const float* __restrict__ as_, const float* __restrict__ ad_,
                          float* __restrict__ ev,
                          const float* __restrict__ b, float* __restrict__ act) {
    int node = blockIdx.x * 8 + (threadIdx.x >> 5);
    if (node >= NN) return;
    int lane = threadIdx.x & 31;
    int g = lane >> 3;
    int q = lane & 7;
    const uint4* hp = (const uint4*)h;
    int begin = rp[node];
    int end = begin + lenv[node];
    float adv = ad_[node];

    // pass 1: sum of exp (logits are O(10), no overflow), spill exp coalesced
    float sum = 0.f;
    for (int e = begin + lane; e < end; e += 32) {
        float p = __expf(lrelu(as_[csr[e]] + adv));
        ev[e] = p;
        sum += p;
    }
#pragma unroll
    for (int o = 16; o; o >>= 1) sum += __shfl_xor_sync(0xffffffffu, sum, o);
    float inv = 1.f / sum;

    // pass 2: weighted gather, quarter-warp per edge, ev read coalesced
    float acc[8];
#pragma unroll
    for (int j = 0; j < 8; j++) acc[j] = 0.f;
    int e = begin;
    for (; e + 8 <= end; e += 8) {
        int eA = e + g, eB = e + 4 + g;
        int sA = csr[eA], sB = csr[eB];
        float aA = ev[eA] * inv;
        float aB = ev[eB] * inv;
        hacc8(hp, sA, q, aA, acc);
        hacc8(hp, sB, q, aB, acc);
    }
    for (; e < end; e += 4) {
        int ee = e + g;
        if (ee < end) hacc8(hp, csr[ee], q, ev[ee] * inv, acc);
    }
    agg_epilogue(acc, b, act, node, lane);
}

// ======== heads + graph embedding (block-reduced atomics + last-block finish) ========
__global__ void k_heads(const float* __restrict__ h,
                        const float* __restrict__ Wopt, const float* __restrict__ bopt,
                        const float* __restrict__ Wb1, const float* __restrict__ bb1,
                        const float* __restrict__ Wb2, const float* __restrict__ bb2,
                        float* __restrict__ out, float* __restrict__ emb,
                        int* __restrict__ ticket, int n) {
    __shared__ float sWopt[640], sbopt[10], sbb1[32], sWb2[32];
    __shared__ float hrow[8][64];
    __shared__ float semb[64];
    __shared__ int islast;
    int tid = threadIdx.x;
    for (int i = tid; i < 640; i += 256) sWopt[i] = Wopt[i];
    if (tid < 10) sbopt[tid] = bopt[tid];
    if (tid < 32) { sbb1[tid] = bb1[tid]; sWb2[tid] = Wb2[tid]; }
    if (tid < 64) semb[tid] = 0.f;
    __syncthreads();
    float bb2v = bb2[0];
    int warp = tid >> 5, lane = tid & 31;
    float wb1r[64];
#pragma unroll
    for (int k = 0; k < 64; k++) wb1r[k] = Wb1[k * 32 + lane];
    float p0 = 0.f, p1 = 0.f;
    bool opt_lane = lane < CC;
    for (int node = blockIdx.x * 8 + warp; node < n; node += gridDim.x * 8) {
        float h0 = h[node * 64 + lane];
        float h1 = h[node * 64 + 32 + lane];
        hrow[warp][lane] = h0;
        hrow[warp][lane + 32] = h1;
        p0 += h0; p1 += h1;
        __syncwarp();
        float t = sbb1[lane];
        float acc = opt_lane ? sbopt[lane] : 0.f;
#pragma unroll
        for (int k = 0; k < 64; k++) {
            float hk = hrow[warp][k];
            t = fmaf(hk, wb1r[k], t);
            if (opt_lane) acc = fmaf(hk, sWopt[k * CC + lane], acc);
        }
        if (opt_lane) out[node * CC + lane] = acc;
        t = fmaxf(t, 0.f) * sWb2[lane];
#pragma unroll
        for (int o = 16; o; o >>= 1) t += __shfl_down_sync(0xffffffffu, t, o);
        if (lane == 0) out[NN * CC + node] = 1.f / (1.f + __expf(-(t + bb2v)));
        __syncwarp();
    }
    atomicAdd(&semb[lane], p0);
    atomicAdd(&semb[lane + 32], p1);
    __syncthreads();
    if (tid < 64) atomicAdd(&emb[tid], semb[tid]);
    __threadfence();
    if (tid == 0) {
        int done = atomicAdd(ticket, 1);
        islast = (done == gridDim.x - 1);
    }
    __syncthreads();
    if (islast) {
        if (tid < 64) out[NN * CC + NN + tid] = emb[tid] * (1.0f / NN);
        if (tid == 0) *ticket = 0;
    }
}

// ======== launch ========
extern "C" void kernel_launch(void* const* d_in, const int* in_sizes, int n_in,
                              void* d_out, int out_size) {
    const float* x    = (const float*)d_in[0];
    const int*   ei   = (const int*)d_in[1];
    const int*   src  = ei;
    const int*   dst  = ei + EE;
    const float* W1   = (const float*)d_in[2];
    const float* b1   = (const float*)d_in[3];
    const float* W2   = (const float*)d_in[4];
    const float* a_s  = (const float*)d_in[5];
    const float* a_d  = (const float*)d_in[6];
    const float* b2   = (const float*)d_in[7];
    const float* W3   = (const float*)d_in[8];
    const float* b3   = (const float*)d_in[9];
    const float* Wopt = (const float*)d_in[10];
    const float* bopt = (const float*)d_in[11];
    const float* Wb1  = (const float*)d_in[12];
    const float* bb1  = (const float*)d_in[13];
    const float* Wb2  = (const float*)d_in[14];
    const float* bb2  = (const float*)d_in[15];
    float* out = (float*)d_out;

    __half* pLin;
    float *pAct, *pDinv, *pAs, *pAd, *pEmb, *pWcsr, *pEv;
    int *pDeg, *pRp, *pLen, *pCur, *pCsr, *pCtr;
    cudaGetSymbolAddress((void**)&pLin,  g_lin);
    cudaGetSymbolAddress((void**)&pAct,  g_act);
    cudaGetSymbolAddress((void**)&pDeg,  g_deg);
    cudaGetSymbolAddress((void**)&pRp,   g_rowptr);
    cudaGetSymbolAddress((void**)&pLen,  g_len);
    cudaGetSymbolAddress((void**)&pCur,  g_cursor);
    cudaGetSymbolAddress((void**)&pCsr,  g_csr);
    cudaGetSymbolAddress((void**)&pWcsr, g_wcsr);
    cudaGetSymbolAddress((void**)&pEv,   g_ev);
    cudaGetSymbolAddress((void**)&pDinv, g_dinv);
    cudaGetSymbolAddress((void**)&pAs,   g_as);
    cudaGetSymbolAddress((void**)&pAd,   g_ad);
    cudaGetSymbolAddress((void**)&pEmb,  g_emb);
    cudaGetSymbolAddress((void**)&pCtr,  g_ctr);

    const int TB = 256;
    const int nBlkA = (NN + 7) / 8;                // warp per node
    const int nBlkG = (NN + 127) / 128;
    const int smem32 = 32 * (64 + 132) * 4;
    const int smem64 = 64 * (64 + 132) * 4;

    static cudaStream_t s1 = nullptr;
    static cudaEvent_t ev0 = nullptr, ev1 = nullptr;
    static int attr_done = 0;
    if (!attr_done) {
        cudaFuncSetAttribute(k_gemm2<64, true>,  cudaFuncAttributeMaxDynamicSharedMemorySize, smem64);
        cudaFuncSetAttribute(k_gemm2<64, false>, cudaFuncAttributeMaxDynamicSharedMemorySize, smem64);
        cudaFuncSetAttribute(k_gemm2<32, false>, cudaFuncAttributeMaxDynamicSharedMemorySize, smem32);
        cudaStreamCreateWithFlags(&s1, cudaStreamNonBlocking);
        cudaEventCreateWithFlags(&ev0, cudaEventDisableTiming);
        cudaEventCreateWithFlags(&ev1, cudaEventDisableTiming);
        attr_done = 1;
    }

    // ---- fork: CSR build on s1, overlapped with GEMM1 on stream 0 ----
    cudaEventRecord(ev0, 0);
    cudaStreamWaitEvent(s1, ev0, 0);
    k_deg_count<<<(EE + 1023) / 1024, TB, 0, s1>>>(dst, pDeg);
    k_rp<<<NB, TB, 0, s1>>>(pDeg, pRp, pCur, pLen, pDinv, pEmb, pCtr);
    k_csr_fill<<<(ET + 1023) / 1024, TB, 0, s1>>>(src, dst, pCur, pCsr, pDinv, pWcsr);
    cudaEventRecord(ev1, s1);

    // ---- GCN layer 1 ----
    k_gemm2<32, false><<<nBlkG, TB, smem32>>>(x, W1, pLin, nullptr, nullptr, nullptr, nullptr, NN);
    cudaStreamWaitEvent(0, ev1, 0);   // join: aggs need CSR + weights
    k_gcn_agg<<<nBlkA, TB>>>(pLin, pRp, pLen, pCsr, pWcsr, b1, pAct);

    // ---- GAT layer (alpha fused into GEMM epilogue) ----
    k_gemm2<64, true><<<nBlkG, TB, smem64>>>(pAct, W2, pLin, a_s, a_d, pAs, pAd, NN);
    k_gat_agg<<<nBlkA, TB>>>(pLin, pRp, pLen, pCsr, pAs, pAd, pEv, b2, pAct);

    // ---- GCN layer 3 ----
    k_gemm2<64, false><<<nBlkG, TB, smem64>>>(pAct, W3, pLin, nullptr, nullptr, nullptr, nullptr, NN);
    k_gcn_agg<<<nBlkA, TB>>>(pLin, pRp, pLen, pCsr, pWcsr, b3, pAct);

    // ---- heads + embedding (finish fused via last-block ticket) ----
    k_heads<<<1184, TB>>>(pAct, Wopt, bopt, Wb1, bb1, Wb2, bb2, out, pEmb, pCtr + 2, NN);
}

// round 10
// speedup vs baseline: 1.0750x; 1.0448x over previous
#include <cuda_runtime.h>
#include <cuda_bf16.h>
#include <cuda_fp16.h>
#include <mma.h>
#include <math.h>

using namespace nvcuda;

#define NN 100000
#define EE 1250000
#define ET (NN + EE)          // edges + self loops
#define CC 10
#define NB 391                // ceil(NN/256)

// -------- scratch (no allocations allowed) --------
__device__ __half g_lin[NN * 64];    // fp16 packed features for gathers
__device__ float g_act[NN * 64];     // fp32 aggregated activations
__device__ int   g_deg[NN];          // starts zero (BSS); re-zeroed by k_rp each launch
__device__ int   g_rowptr[NN];
__device__ int   g_len[NN];
__device__ int   g_cursor[NN];
__device__ int   g_csr[ET];
__device__ float g_wcsr[ET];         // per-slot GCN norm (written in csr_fill)
__device__ float g_ev[ET];           // per-slot GAT exp(logit)
__device__ float g_dinv[NN];
__device__ float g_as[NN];
__device__ float g_ad[NN];
__device__ float g_emb[64];
__device__ int   g_ctr[4];           // [0]=rp base, [1]=rp ticket, [2]=heads ticket

// ======== CSR build ========
__global__ void k_deg_count(const int* __restrict__ dst, int* deg) {
    int t0 = blockIdx.x * 1024 + threadIdx.x;
#pragma unroll
    for (int j = 0; j < 4; j++) {
        int i = t0 + j * 256;
        if (i < EE) atomicAdd(&deg[dst[i]], 1);
    }
}
// fused: block scan + atomic base -> rowptr/cursor/len/dinv; zeroes deg + emb; resets ctr
__global__ void k_rp(int* __restrict__ deg, int* __restrict__ rp, int* __restrict__ cur,
                     int* __restrict__ len, float* __restrict__ dinv,
                     float* __restrict__ emb, int* __restrict__ ctr) {
    __shared__ int s[256];
    __shared__ int base;
    int t = threadIdx.x;
    int i = blockIdx.x * 256 + t;
    int v = (i < NN) ? (deg[i] + 1) : 0;       // +1 self loop
    s[t] = v;
    __syncthreads();
    for (int off = 1; off < 256; off <<= 1) {
        int u = (t >= off) ? s[t - off] : 0;
        __syncthreads();
        s[t] += u;
        __syncthreads();
    }
    if (t == 255) base = atomicAdd(&ctr[0], s[255]);
    __syncthreads();
    if (i < NN) {
        int ex = base + s[t] - v;
        rp[i] = ex;
        cur[i] = ex;
        len[i] = v;
        dinv[i] = rsqrtf((float)v);
        deg[i] = 0;                            // ready for next replay
    }
    if (blockIdx.x == 0 && t < 64) emb[t] = 0.f;
    __threadfence();
    if (t == 0) {
        int done = atomicAdd(&ctr[1], 1);
        if (done == gridDim.x - 1) { ctr[0] = 0; ctr[1] = 0; }
    }
}
// fills csr AND the GCN edge weights (dinv ready by now)
__global__ void k_csr_fill(const int* __restrict__ src, const int* __restrict__ dst,
                           int* __restrict__ cur, int* __restrict__ csr,
                           const float* __restrict__ dinv, float* __restrict__ wcsr) {
    int t0 = blockIdx.x * 1024 + threadIdx.x;
#pragma unroll
    for (int j = 0; j < 4; j++) {
        int i = t0 + j * 256;
        if (i < ET) {
            int s, d;
            if (i < EE) { s = src[i]; d = dst[i]; } else { s = d = i - EE; }
            int pos = atomicAdd(&cur[d], 1);
            csr[pos] = s;
            wcsr[pos] = dinv[s] * dinv[d];
        }
    }
}

// ======== tensor-core GEMM: C_h[M,64] = A[M,K] @ W[K,64], fp16 in / fp32 accum ========
// smem: As[128][K+8] half, Ws[K][72] half, Os[128][68] float
template <int K, bool ALPHA>
__global__ void k_gemm_t(const float* __restrict__ A, const float* __restrict__ W,
                         __half* __restrict__ C,
                         const float* __restrict__ avs, const float* __restrict__ avd,
                         float* __restrict__ as_out, float* __restrict__ ad_out, int M) {
    extern __shared__ char smx[];
    const int AS = K + 8;
    __half* As = (__half*)smx;
    __half* Ws = As + 128 * AS;
    float*  Os = (float*)(smx + 128 * AS * 2 + K * 72 * 2);
    int tid = threadIdx.x;
    int base = blockIdx.x * 128;

    for (int idx = tid; idx < K * 64; idx += 256)
        Ws[(idx >> 6) * 72 + (idx & 63)] = __float2half(W[idx]);
    for (int idx = tid; idx < 128 * K; idx += 256) {
        int r = idx / K, k = idx - r * K;
        int row = base + r;
        As[r * AS + k] = __float2half(row < M ? A[row * K + k] : 0.f);
    }
    __syncthreads();

    int w = tid >> 5;
    wmma::fragment<wmma::matrix_a, 16, 16, 16, __half, wmma::row_major> fa;
    wmma::fragment<wmma::matrix_b, 16, 16, 16, __half, wmma::row_major> fb;
    wmma::fragment<wmma::accumulator, 16, 16, 16, float> fc[4];
#pragma unroll
    for (int j = 0; j < 4; j++) wmma::fill_fragment(fc[j], 0.f);
#pragma unroll
    for (int kk = 0; kk < K / 16; kk++) {
        wmma::load_matrix_sync(fa, As + w * 16 * AS + kk * 16, AS);
#pragma unroll
        for (int j = 0; j < 4; j++) {
            wmma::load_matrix_sync(fb, Ws + kk * 16 * 72 + j * 16, 72);
            wmma::mma_sync(fc[j], fa, fb, fc[j]);
        }
    }
#pragma unroll
    for (int j = 0; j < 4; j++)
        wmma::store_matrix_sync(Os + w * 16 * 68 + j * 16, fc[j], 68, wmma::mem_row_major);
    __syncthreads();

    // epilogue: thread t -> row t>>1, 32-col half (t&1)
    int r = tid >> 1, ch = (tid & 1) * 32;
    int row = base + r;
    float f[32];
#pragma unroll
    for (int i = 0; i < 8; i++) {
        float4 v = *(float4*)&Os[r * 68 + ch + i * 4];
        f[i * 4] = v.x; f[i * 4 + 1] = v.y; f[i * 4 + 2] = v.z; f[i * 4 + 3] = v.w;
    }
    if (row < M) {
        __half2 hh[16];
#pragma unroll
        for (int i = 0; i < 16; i++)
            hh[i] = __float22half2_rn(make_float2(f[2 * i], f[2 * i + 1]));
#pragma unroll
        for (int i = 0; i < 4; i++)
            *(uint4*)&C[row * 64 + ch + i * 8] = ((uint4*)hh)[i];
    }
    if (ALPHA) {
        float sp = 0.f, dp = 0.f;
#pragma unroll
        for (int i = 0; i < 32; i++) {
            sp = fmaf(f[i], avs[ch + i], sp);
            dp = fmaf(f[i], avd[ch + i], dp);
        }
        sp += __shfl_xor_sync(0xffffffffu, sp, 1);
        dp += __shfl_xor_sync(0xffffffffu, dp, 1);
        if ((tid & 1) == 0 && row < M) { as_out[row] = sp; ad_out[row] = dp; }
    }
}

// ======== quarter-warp gather: lane q in group holds halves 8q..8q+7 ========
__device__ __forceinline__ void hacc8(const uint4* __restrict__ hp, int s, int q, float m,
                                      float acc[8]) {
    uint4 rv = hp[(unsigned)s * 8 + q];
    float2 f0 = __half22float2(*(__half2*)&rv.x);
    float2 f1 = __half22float2(*(__half2*)&rv.y);
    float2 f2 = __half22float2(*(__half2*)&rv.z);
    float2 f3 = __half22float2(*(__half2*)&rv.w);
    acc[0] = fmaf(f0.x, m, acc[0]); acc[1] = fmaf(f0.y, m, acc[1]);
    acc[2] = fmaf(f1.x, m, acc[2]); acc[3] = fmaf(f1.y, m, acc[3]);
    acc[4] = fmaf(f2.x, m, acc[4]); acc[5] = fmaf(f2.y, m, acc[5]);
    acc[6] = fmaf(f3.x, m, acc[6]); acc[7] = fmaf(f3.y, m, acc[7]);
}

__device__ __forceinline__ void agg_epilogue(float acc[8], const float* __restrict__ b,
                                             float* __restrict__ act, int node, int lane) {
#pragma unroll
    for (int j = 0; j < 8; j++) {
        acc[j] += __shfl_xor_sync(0xffffffffu, acc[j], 8);
        acc[j] += __shfl_xor_sync(0xffffffffu, acc[j], 16);
    }
    if (lane < 8) {
        int fi = lane * 8;
        float4 b0 = *(const float4*)&b[fi];
        float4 b1 = *(const float4*)&b[fi + 4];
        float4 o0 = make_float4(fmaxf(acc[0] + b0.x, 0.f), fmaxf(acc[1] + b0.y, 0.f),
                                fmaxf(acc[2] + b0.z, 0.f), fmaxf(acc[3] + b0.w, 0.f));
        float4 o1 = make_float4(fmaxf(acc[4] + b1.x, 0.f), fmaxf(acc[5] + b1.y, 0.f),
                                fmaxf(acc[6] + b1.z, 0.f), fmaxf(acc[7] + b1.w, 0.f));
        *(float4*)&act[node * 64 + fi]     = o0;
        *(float4*)&act[node * 64 + fi + 4] = o1;
    }
}

// ======== GCN aggregation: warp per node, quarter-warp per edge ========
__global__ void k_gcn_agg(const __half* __restrict__ h, const int* __restrict__ rp,
                          const int* __restrict__ lenv, const int* __restrict__ csr,
                          const float* __restrict__ wcsr,
                          const float* __restrict__ b, float* __restrict__ act) {
    int node = blockIdx.x * 8 + (threadIdx.x >> 5);
    if (node >= NN) return;
    int lane = threadIdx.x & 31;
    int g = lane >> 3;          // quarter id
    int q = lane & 7;           // lane in quarter
    const uint4* hp = (const uint4*)h;
    int e = rp[node];
    int end = e + lenv[node];
    float acc[8];
#pragma unroll
    for (int j = 0; j < 8; j++) acc[j] = 0.f;
    for (; e + 8 <= end; e += 8) {
        int eA = e + g, eB = e + 4 + g;
        int sA = csr[eA], sB = csr[eB];
        float mA = wcsr[eA], mB = wcsr[eB];
        hacc8(hp, sA, q, mA, acc);
        hacc8(hp, sB, q, mB, acc);
    }
    for (; e < end; e += 4) {
        int ee = e + g;
        if (ee < end) hacc8(hp, csr[ee], q, wcsr[ee], acc);
    }
    agg_epilogue(acc, b, act, node, lane);
}

__device__ __forceinline__ float lrelu(float v) { return v >= 0.f ? v : 0.2f * v; }

// ======== fused GAT aggregation: no-max softmax + exp spill + weighted gather ========
__global__ void k_gat_agg(const __half* __restrict__ h, const int* __restrict__ rp,
                          const int* __restrict__ lenv, const int* __restrict__ csr,
                          const float* __restrict__ as_, const float* __restrict__ ad_,
                          float* __restrict__ ev,
                          const float* __restrict__ b, float* __restrict__ act) {
    int node = blockIdx.x * 8 + (threadIdx.x >> 5);
    if (node >= NN) return;
    int lane = threadIdx.x & 31;
    int g = lane >> 3;
    int q = lane & 7;
    const uint4* hp = (const uint4*)h;
    int begin = rp[node];
    int end = begin + lenv[node];
    float adv = ad_[node];

    float sum = 0.f;
    for (int e = begin + lane; e < end; e += 32) {
        float p = __expf(lrelu(as_[csr[e]] + adv));
        ev[e] = p;
        sum += p;
    }
#pragma unroll
    for (int o = 16; o; o >>= 1) sum += __shfl_xor_sync(0xffffffffu, sum, o);
    float inv = 1.f / sum;

    float acc[8];
#pragma unroll
    for (int j = 0; j < 8; j++) acc[j] = 0.f;
    int e = begin;
    for (; e + 8 <= end; e += 8) {
        int eA = e + g, eB = e + 4 + g;
        int sA = csr[eA], sB = csr[eB];
        float aA = ev[eA] * inv;
        float aB = ev[eB] * inv;
        hacc8(hp, sA, q, aA, acc);
        hacc8(hp, sB, q, aB, acc);
    }
    for (; e < end; e += 4) {
        int ee = e + g;
        if (ee < end) hacc8(hp, csr[ee], q, ev[ee] * inv, acc);
    }
    agg_epilogue(acc, b, act, node, lane);
}

// ======== heads + graph embedding (block-reduced atomics + last-block finish) ========
__global__ void k_heads(const float* __restrict__ h,
                        const float* __restrict__ Wopt, const float* __restrict__ bopt,
                        const float* __restrict__ Wb1, const float* __restrict__ bb1,
                        const float* __restrict__ Wb2, const float* __restrict__ bb2,
                        float* __restrict__ out, float* __restrict__ emb,
                        int* __restrict__ ticket, int n) {
    __shared__ float sWopt[640], sbopt[10], sbb1[32], sWb2[32];
    __shared__ float hrow[8][64];
    __shared__ float semb[64];
    __shared__ int islast;
    int tid = threadIdx.x;
    for (int i = tid; i < 640; i += 256) sWopt[i] = Wopt[i];
    if (tid < 10) sbopt[tid] = bopt[tid];
    if (tid < 32) { sbb1[tid] = bb1[tid]; sWb2[tid] = Wb2[tid]; }
    if (tid < 64) semb[tid] = 0.f;
    __syncthreads();
    float bb2v = bb2[0];
    int warp = tid >> 5, lane = tid & 31;
    float wb1r[64];
#pragma unroll
    for (int k = 0; k < 64; k++) wb1r[k] = Wb1[k * 32 + lane];
    float p0 = 0.f, p1 = 0.f;
    bool opt_lane = lane < CC;
    for (int node = blockIdx.x * 8 + warp; node < n; node += gridDim.x * 8) {
        float h0 = h[node * 64 + lane];
        float h1 = h[node * 64 + 32 + lane];
        hrow[warp][lane] = h0;
        hrow[warp][lane + 32] = h1;
        p0 += h0; p1 += h1;
        __syncwarp();
        float t = sbb1[lane];
        float acc = opt_lane ? sbopt[lane] : 0.f;
#pragma unroll
        for (int k = 0; k < 64; k++) {
            float hk = hrow[warp][k];
            t = fmaf(hk, wb1r[k], t);
            if (opt_lane) acc = fmaf(hk, sWopt[k * CC + lane], acc);
        }
        if (opt_lane) out[node * CC + lane] = acc;
        t = fmaxf(t, 0.f) * sWb2[lane];
#pragma unroll
        for (int o = 16; o; o >>= 1) t += __shfl_down_sync(0xffffffffu, t, o);
        if (lane == 0) out[NN * CC + node] = 1.f / (1.f + __expf(-(t + bb2v)));
        __syncwarp();
    }
    atomicAdd(&semb[lane], p0);
    atomicAdd(&semb[lane + 32], p1);
    __syncthreads();
    if (tid < 64) atomicAdd(&emb[tid], semb[tid]);
    __threadfence();
    if (tid == 0) {
        int done = atomicAdd(ticket, 1);
        islast = (done == gridDim.x - 1);
    }
    __syncthreads();
    if (islast) {
        if (tid < 64) out[NN * CC + NN + tid] = emb[tid] * (1.0f / NN);
        if (tid == 0) *ticket = 0;
    }
}

// ======== launch ========
extern "C" void kernel_launch(void* const* d_in, const int* in_sizes, int n_in,
                              void* d_out, int out_size) {
    const float* x    = (const float*)d_in[0];
    const int*   ei   = (const int*)d_in[1];
    const int*   src  = ei;
    const int*   dst  = ei + EE;
    const float* W1   = (const float*)d_in[2];
    const float* b1   = (const float*)d_in[3];
    const float* W2   = (const float*)d_in[4];
    const float* a_s  = (const float*)d_in[5];
    const float* a_d  = (const float*)d_in[6];
    const float* b2   = (const float*)d_in[7];
    const float* W3   = (const float*)d_in[8];
    const float* b3   = (const float*)d_in[9];
    const float* Wopt = (const float*)d_in[10];
    const float* bopt = (const float*)d_in[11];
    const float* Wb1  = (const float*)d_in[12];
    const float* bb1  = (const float*)d_in[13];
    const float* Wb2  = (const float*)d_in[14];
    const float* bb2  = (const float*)d_in[15];
    float* out = (float*)d_out;

    __half* pLin;
    float *pAct, *pDinv, *pAs, *pAd, *pEmb, *pWcsr, *pEv;
    int *pDeg, *pRp, *pLen, *pCur, *pCsr, *pCtr;
    cudaGetSymbolAddress((void**)&pLin,  g_lin);
    cudaGetSymbolAddress((void**)&pAct,  g_act);
    cudaGetSymbolAddress((void**)&pDeg,  g_deg);
    cudaGetSymbolAddress((void**)&pRp,   g_rowptr);
    cudaGetSymbolAddress((void**)&pLen,  g_len);
    cudaGetSymbolAddress((void**)&pCur,  g_cursor);
    cudaGetSymbolAddress((void**)&pCsr,  g_csr);
    cudaGetSymbolAddress((void**)&pWcsr, g_wcsr);
    cudaGetSymbolAddress((void**)&pEv,   g_ev);
    cudaGetSymbolAddress((void**)&pDinv, g_dinv);
    cudaGetSymbolAddress((void**)&pAs,   g_as);
    cudaGetSymbolAddress((void**)&pAd,   g_ad);
    cudaGetSymbolAddress((void**)&pEmb,  g_emb);
    cudaGetSymbolAddress((void**)&pCtr,  g_ctr);

    const int TB = 256;
    const int nBlkA = (NN + 7) / 8;                // warp per node
    const int nBlkG = (NN + 127) / 128;
    const int smemT32 = 128 * 40 * 2 + 32 * 72 * 2 + 128 * 68 * 4;   // 49664
    const int smemT64 = 128 * 72 * 2 + 64 * 72 * 2 + 128 * 68 * 4;   // 62464

    static cudaStream_t s1 = nullptr;
    static cudaEvent_t ev0 = nullptr, ev1 = nullptr;
    static int attr_done = 0;
    if (!attr_done) {
        cudaFuncSetAttribute(k_gemm_t<64, true>,  cudaFuncAttributeMaxDynamicSharedMemorySize, smemT64);
        cudaFuncSetAttribute(k_gemm_t<64, false>, cudaFuncAttributeMaxDynamicSharedMemorySize, smemT64);
        cudaFuncSetAttribute(k_gemm_t<32, false>, cudaFuncAttributeMaxDynamicSharedMemorySize, smemT32);
        cudaStreamCreateWithFlags(&s1, cudaStreamNonBlocking);
        cudaEventCreateWithFlags(&ev0, cudaEventDisableTiming);
        cudaEventCreateWithFlags(&ev1, cudaEventDisableTiming);
        attr_done = 1;
    }

    // ---- fork: CSR build on s1, overlapped with GEMM1 on stream 0 ----
    cudaEventRecord(ev0, 0);
    cudaStreamWaitEvent(s1, ev0, 0);
    k_deg_count<<<(EE + 1023) / 1024, TB, 0, s1>>>(dst, pDeg);
    k_rp<<<NB, TB, 0, s1>>>(pDeg, pRp, pCur, pLen, pDinv, pEmb, pCtr);
    k_csr_fill<<<(ET + 1023) / 1024, TB, 0, s1>>>(src, dst, pCur, pCsr, pDinv, pWcsr);
    cudaEventRecord(ev1, s1);

    // ---- GCN layer 1 ----
    k_gemm_t<32, false><<<nBlkG, TB, smemT32>>>(x, W1, pLin, nullptr, nullptr, nullptr, nullptr, NN);
    cudaStreamWaitEvent(0, ev1, 0);   // join: aggs need CSR + weights
    k_gcn_agg<<<nBlkA, TB>>>(pLin, pRp, pLen, pCsr, pWcsr, b1, pAct);

    // ---- GAT layer (alpha fused into GEMM epilogue) ----
    k_gemm_t<64, true><<<nBlkG, TB, smemT64>>>(pAct, W2, pLin, a_s, a_d, pAs, pAd, NN);
    k_gat_agg<<<nBlkA, TB>>>(pLin, pRp, pLen, pCsr, pAs, pAd, pEv, b2, pAct);

    // ---- GCN layer 3 ----
    k_gemm_t<64, false><<<nBlkG, TB, smemT64>>>(pAct, W3, pLin, nullptr, nullptr, nullptr, nullptr, NN);
    k_gcn_agg<<<nBlkA, TB>>>(pLin, pRp, pLen, pCsr, pWcsr, b3, pAct);

    // ---- heads + embedding (finish fused via last-block ticket) ----
    k_heads<<<1184, TB>>>(pAct, Wopt, bopt, Wb1, bb1, Wb2, bb2, out, pEmb, pCtr + 2, NN);
}

// round 12
// speedup vs baseline: 1.2525x; 1.1651x over previous
#include <cuda_runtime.h>
#include <cuda_bf16.h>
#include <cuda_fp16.h>
#include <mma.h>
#include <math.h>

using namespace nvcuda;

#define NN 100000
#define EE 1250000
#define ET (NN + EE)          // edges + self loops
#define CC 10
#define NB 391                // ceil(NN/256)

// -------- scratch (no allocations allowed) --------
__device__ __half g_lin[NN * 64];    // fp16 packed features for gathers
__device__ float g_act[NN * 64];     // fp32 aggregated activations
__device__ int   g_deg[NN];          // starts zero (BSS); re-zeroed by k_rp each launch
__device__ int   g_rowptr[NN];
__device__ int   g_len[NN];
__device__ int   g_cursor[NN];
__device__ int   g_csr[ET];
__device__ float g_wcsr[ET];         // per-slot GCN norm (written in csr_fill)
__device__ float g_ev[ET];           // per-slot GAT exp(logit)
__device__ float g_dinv[NN];
__device__ float g_as[NN];
__device__ float g_ad[NN];
__device__ float g_emb[64];
__device__ int   g_ctr[4];           // [0]=rp base, [1]=rp ticket, [2]=heads ticket

// ======== CSR build ========
__global__ void k_deg_count(const int* __restrict__ dst, int* deg) {
    int t0 = blockIdx.x * 1024 + threadIdx.x;
#pragma unroll
    for (int j = 0; j < 4; j++) {
        int i = t0 + j * 256;
        if (i < EE) atomicAdd(&deg[dst[i]], 1);
    }
}
// fused: block scan + atomic base -> rowptr/cursor/len/dinv; zeroes deg + emb; resets ctr
__global__ void k_rp(int* __restrict__ deg, int* __restrict__ rp, int* __restrict__ cur,
                     int* __restrict__ len, float* __restrict__ dinv,
                     float* __restrict__ emb, int* __restrict__ ctr) {
    __shared__ int s[256];
    __shared__ int base;
    int t = threadIdx.x;
    int i = blockIdx.x * 256 + t;
    int v = (i < NN) ? (deg[i] + 1) : 0;       // +1 self loop
    s[t] = v;
    __syncthreads();
    for (int off = 1; off < 256; off <<= 1) {
        int u = (t >= off) ? s[t - off] : 0;
        __syncthreads();
        s[t] += u;
        __syncthreads();
    }
    if (t == 255) base = atomicAdd(&ctr[0], s[255]);
    __syncthreads();
    if (i < NN) {
        int ex = base + s[t] - v;
        rp[i] = ex;
        cur[i] = ex;
        len[i] = v;
        dinv[i] = rsqrtf((float)v);
        deg[i] = 0;                            // ready for next replay
    }
    if (blockIdx.x == 0 && t < 64) emb[t] = 0.f;
    __threadfence();
    if (t == 0) {
        int done = atomicAdd(&ctr[1], 1);
        if (done == gridDim.x - 1) { ctr[0] = 0; ctr[1] = 0; }
    }
}
// fills csr AND the GCN edge weights (dinv ready by now)
__global__ void k_csr_fill(const int* __restrict__ src, const int* __restrict__ dst,
                           int* __restrict__ cur, int* __restrict__ csr,
                           const float* __restrict__ dinv, float* __restrict__ wcsr) {
    int t0 = blockIdx.x * 1024 + threadIdx.x;
#pragma unroll
    for (int j = 0; j < 4; j++) {
        int i = t0 + j * 256;
        if (i < ET) {
            int s, d;
            if (i < EE) { s = src[i]; d = dst[i]; } else { s = d = i - EE; }
            int pos = atomicAdd(&cur[d], 1);
            csr[pos] = s;
            wcsr[pos] = dinv[s] * dinv[d];
        }
    }
}

// ======== tensor-core GEMM: C_h[M,64] = A[M,K] @ W[K,64], fp16 in / fp32 accum ========
// smem layout: phase 1: As[128][K+8] half, Ws[K][72] half.  phase 2 (overlaid): Os[128][68] float.
__device__ __forceinline__ uint2 cvt4(float4 v) {
    __half2 h0 = __float22half2_rn(make_float2(v.x, v.y));
    __half2 h1 = __float22half2_rn(make_float2(v.z, v.w));
    uint2 r;
    r.x = *(unsigned*)&h0;
    r.y = *(unsigned*)&h1;
    return r;
}

template <int K, bool ALPHA>
__global__ void k_gemm_t(const float* __restrict__ A, const float* __restrict__ W,
                         __half* __restrict__ C,
                         const float* __restrict__ avs, const float* __restrict__ avd,
                         float* __restrict__ as_out, float* __restrict__ ad_out, int M) {
    extern __shared__ char smx[];
    const int AS = K + 8;                       // halves per As row
    __half* As = (__half*)smx;                  // 128*AS halves
    __half* Ws = As + 128 * AS;                 // K*72 halves
    float*  Os = (float*)smx;                   // OVERLAY (As/Ws dead after mainloop)
    int tid = threadIdx.x;
    int base = blockIdx.x * 128;

    // W: K*64 floats, float4-vectorized
    for (int idx = tid; idx < K * 16; idx += 256) {
        int r = idx >> 4, c4 = (idx & 15) * 4;
        float4 v = *(const float4*)&W[r * 64 + c4];
        *(uint2*)&Ws[r * 72 + c4] = cvt4(v);
    }
    // A: 128*K floats, float4-vectorized
    const int RQ = K / 4;                       // float4s per row
    for (int idx = tid; idx < 128 * RQ; idx += 256) {
        int r = idx / RQ, c4 = (idx - r * RQ) * 4;
        int row = base + r;
        float4 v = (row < M) ? *(const float4*)&A[row * K + c4]
                             : make_float4(0.f, 0.f, 0.f, 0.f);
        *(uint2*)&As[r * AS + c4] = cvt4(v);
    }
    __syncthreads();

    int w = tid >> 5;
    wmma::fragment<wmma::matrix_a, 16, 16, 16, __half, wmma::row_major> fa;
    wmma::fragment<wmma::matrix_b, 16, 16, 16, __half, wmma::row_major> fb;
    wmma::fragment<wmma::accumulator, 16, 16, 16, float> fc[4];
#pragma unroll
    for (int j = 0; j < 4; j++) wmma::fill_fragment(fc[j], 0.f);
#pragma unroll
    for (int kk = 0; kk < K / 16; kk++) {
        wmma::load_matrix_sync(fa, As + w * 16 * AS + kk * 16, AS);
#pragma unroll
        for (int j = 0; j < 4; j++) {
            wmma::load_matrix_sync(fb, Ws + kk * 16 * 72 + j * 16, 72);
            wmma::mma_sync(fc[j], fa, fb, fc[j]);
        }
    }
    __syncthreads();                            // all reads of As/Ws complete before overlay
#pragma unroll
    for (int j = 0; j < 4; j++)
        wmma::store_matrix_sync(Os + w * 16 * 68 + j * 16, fc[j], 68, wmma::mem_row_major);
    __syncthreads();

    // epilogue: thread t -> row t>>1, 32-col half (t&1)
    int r = tid >> 1, ch = (tid & 1) * 32;
    int row = base + r;
    float f[32];
#pragma unroll
    for (int i = 0; i < 8; i++) {
        float4 v = *(float4*)&Os[r * 68 + ch + i * 4];
        f[i * 4] = v.x; f[i * 4 + 1] = v.y; f[i * 4 + 2] = v.z; f[i * 4 + 3] = v.w;
    }
    if (row < M) {
        __half2 hh[16];
#pragma unroll
        for (int i = 0; i < 16; i++)
            hh[i] = __float22half2_rn(make_float2(f[2 * i], f[2 * i + 1]));
#pragma unroll
        for (int i = 0; i < 4; i++)
            *(uint4*)&C[row * 64 + ch + i * 8] = ((uint4*)hh)[i];
    }
    if (ALPHA) {
        float sp = 0.f, dp = 0.f;
#pragma unroll
        for (int i = 0; i < 32; i++) {
            sp = fmaf(f[i], avs[ch + i], sp);
            dp = fmaf(f[i], avd[ch + i], dp);
        }
        sp += __shfl_xor_sync(0xffffffffu, sp, 1);
        dp += __shfl_xor_sync(0xffffffffu, dp, 1);
        if ((tid & 1) == 0 && row < M) { as_out[row] = sp; ad_out[row] = dp; }
    }
}

// ======== quarter-warp gather: lane q in group holds halves 8q..8q+7 ========
__device__ __forceinline__ void hacc8(const uint4* __restrict__ hp, int s, int q, float m,
                                      float acc[8]) {
    uint4 rv = hp[(unsigned)s * 8 + q];
    float2 f0 = __half22float2(*(__half2*)&rv.x);
    float2 f1 = __half22float2(*(__half2*)&rv.y);
    float2 f2 = __half22float2(*(__half2*)&rv.z);
    float2 f3 = __half22float2(*(__half2*)&rv.w);
    acc[0] = fmaf(f0.x, m, acc[0]); acc[1] = fmaf(f0.y, m, acc[1]);
    acc[2] = fmaf(f1.x, m, acc[2]); acc[3] = fmaf(f1.y, m, acc[3]);
    acc[4] = fmaf(f2.x, m, acc[4]); acc[5] = fmaf(f2.y, m, acc[5]);
    acc[6] = fmaf(f3.x, m, acc[6]); acc[7] = fmaf(f3.y, m, acc[7]);
}

__device__ __forceinline__ void agg_epilogue(float acc[8], const float* __restrict__ b,
                                             float* __restrict__ act, int node, int lane) {
#pragma unroll
    for (int j = 0; j < 8; j++) {
        acc[j] += __shfl_xor_sync(0xffffffffu, acc[j], 8);
        acc[j] += __shfl_xor_sync(0xffffffffu, acc[j], 16);
    }
    if (lane < 8) {
        int fi = lane * 8;
        float4 b0 = *(const float4*)&b[fi];
        float4 b1 = *(const float4*)&b[fi + 4];
        float4 o0 = make_float4(fmaxf(acc[0] + b0.x, 0.f), fmaxf(acc[1] + b0.y, 0.f),
                                fmaxf(acc[2] + b0.z, 0.f), fmaxf(acc[3] + b0.w, 0.f));
        float4 o1 = make_float4(fmaxf(acc[4] + b1.x, 0.f), fmaxf(acc[5] + b1.y, 0.f),
                                fmaxf(acc[6] + b1.z, 0.f), fmaxf(acc[7] + b1.w, 0.f));
        *(float4*)&act[node * 64 + fi]     = o0;
        *(float4*)&act[node * 64 + fi + 4] = o1;
    }
}

// ======== GCN aggregation: warp per node, quarter-warp per edge ========
__global__ void k_gcn_agg(const __half* __restrict__ h, const int* __restrict__ rp,
                          const int* __restrict__ lenv, const int* __restrict__ csr,
                          const float* __restrict__ wcsr,
                          const float* __restrict__ b, float* __restrict__ act) {
    int node = blockIdx.x * 8 + (threadIdx.x >> 5);
    if (node >= NN) return;
    int lane = threadIdx.x & 31;
    int g = lane >> 3;          // quarter id
    int q = lane & 7;           // lane in quarter
    const uint4* hp = (const uint4*)h;
    int e = rp[node];
    int end = e + lenv[node];
    float acc[8];
#pragma unroll
    for (int j = 0; j < 8; j++) acc[j] = 0.f;
    for (; e + 8 <= end; e += 8) {
        int eA = e + g, eB = e + 4 + g;
        int sA = csr[eA], sB = csr[eB];
        float mA = wcsr[eA], mB = wcsr[eB];
        hacc8(hp, sA, q, mA, acc);
        hacc8(hp, sB, q, mB, acc);
    }
    for (; e < end; e += 4) {
        int ee = e + g;
        if (ee < end) hacc8(hp, csr[ee], q, wcsr[ee], acc);
    }
    agg_epilogue(acc, b, act, node, lane);
}

__device__ __forceinline__ float lrelu(float v) { return v >= 0.f ? v : 0.2f * v; }

// ======== fused GAT aggregation: no-max softmax + exp spill + weighted gather ========
__global__ void k_gat_agg(const __half* __restrict__ h, const int* __restrict__ rp,
                          const int* __restrict__ lenv, const int* __restrict__ csr,
                          const float* __restrict__ as_, const float* __restrict__ ad_,
                          float* __restrict__ ev,
                          const float* __restrict__ b, float* __restrict__ act) {
    int node = blockIdx.x * 8 + (threadIdx.x >> 5);
    if (node >= NN) return;
    int lane = threadIdx.x & 31;
    int g = lane >> 3;
    int q = lane & 7;
    const uint4* hp = (const uint4*)h;
    int begin = rp[node];
    int end = begin + lenv[node];
    float adv = ad_[node];

    float sum = 0.f;
    for (int e = begin + lane; e < end; e += 32) {
        float p = __expf(lrelu(as_[csr[e]] + adv));
        ev[e] = p;
        sum += p;
    }
#pragma unroll
    for (int o = 16; o; o >>= 1) sum += __shfl_xor_sync(0xffffffffu, sum, o);
    float inv = 1.f / sum;

    float acc[8];
#pragma unroll
    for (int j = 0; j < 8; j++) acc[j] = 0.f;
    int e = begin;
    for (; e + 8 <= end; e += 8) {
        int eA = e + g, eB = e + 4 + g;
        int sA = csr[eA], sB = csr[eB];
        float aA = ev[eA] * inv;
        float aB = ev[eB] * inv;
        hacc8(hp, sA, q, aA, acc);
        hacc8(hp, sB, q, aB, acc);
    }
    for (; e < end; e += 4) {
        int ee = e + g;
        if (ee < end) hacc8(hp, csr[ee], q, ev[ee] * inv, acc);
    }
    agg_epilogue(acc, b, act, node, lane);
}

// ======== heads + graph embedding (block-reduced atomics + last-block finish) ========
__global__ void k_heads(const float* __restrict__ h,
                        const float* __restrict__ Wopt, const float* __restrict__ bopt,
                        const float* __restrict__ Wb1, const float* __restrict__ bb1,
                        const float* __restrict__ Wb2, const float* __restrict__ bb2,
                        float* __restrict__ out, float* __restrict__ emb,
                        int* __restrict__ ticket, int n) {
    __shared__ float sWopt[640], sbopt[10], sbb1[32], sWb2[32];
    __shared__ float hrow[8][64];
    __shared__ float semb[64];
    __shared__ int islast;
    int tid = threadIdx.x;
    for (int i = tid; i < 640; i += 256) sWopt[i] = Wopt[i];
    if (tid < 10) sbopt[tid] = bopt[tid];
    if (tid < 32) { sbb1[tid] = bb1[tid]; sWb2[tid] = Wb2[tid]; }
    if (tid < 64) semb[tid] = 0.f;
    __syncthreads();
    float bb2v = bb2[0];
    int warp = tid >> 5, lane = tid & 31;
    float wb1r[64];
#pragma unroll
    for (int k = 0; k < 64; k++) wb1r[k] = Wb1[k * 32 + lane];
    float p0 = 0.f, p1 = 0.f;
    bool opt_lane = lane < CC;
    for (int node = blockIdx.x * 8 + warp; node < n; node += gridDim.x * 8) {
        float h0 = h[node * 64 + lane];
        float h1 = h[node * 64 + 32 + lane];
        hrow[warp][lane] = h0;
        hrow[warp][lane + 32] = h1;
        p0 += h0; p1 += h1;
        __syncwarp();
        float t = sbb1[lane];
        float acc = opt_lane ? sbopt[lane] : 0.f;
#pragma unroll
        for (int k = 0; k < 64; k++) {
            float hk = hrow[warp][k];
            t = fmaf(hk, wb1r[k], t);
            if (opt_lane) acc = fmaf(hk, sWopt[k * CC + lane], acc);
        }
        if (opt_lane) out[node * CC + lane] = acc;
        t = fmaxf(t, 0.f) * sWb2[lane];
#pragma unroll
        for (int o = 16; o; o >>= 1) t += __shfl_down_sync(0xffffffffu, t, o);
        if (lane == 0) out[NN * CC + node] = 1.f / (1.f + __expf(-(t + bb2v)));
        __syncwarp();
    }
    atomicAdd(&semb[lane], p0);
    atomicAdd(&semb[lane + 32], p1);
    __syncthreads();
    if (tid < 64) atomicAdd(&emb[tid], semb[tid]);
    __threadfence();
    if (tid == 0) {
        int done = atomicAdd(ticket, 1);
        islast = (done == gridDim.x - 1);
    }
    __syncthreads();
    if (islast) {
        if (tid < 64) out[NN * CC + NN + tid] = emb[tid] * (1.0f / NN);
        if (tid == 0) *ticket = 0;
    }
}

// ======== launch ========
extern "C" void kernel_launch(void* const* d_in, const int* in_sizes, int n_in,
                              void* d_out, int out_size) {
    const float* x    = (const float*)d_in[0];
    const int*   ei   = (const int*)d_in[1];
    const int*   src  = ei;
    const int*   dst  = ei + EE;
    const float* W1   = (const float*)d_in[2];
    const float* b1   = (const float*)d_in[3];
    const float* W2   = (const float*)d_in[4];
    const float* a_s  = (const float*)d_in[5];
    const float* a_d  = (const float*)d_in[6];
    const float* b2   = (const float*)d_in[7];
    const float* W3   = (const float*)d_in[8];
    const float* b3   = (const float*)d_in[9];
    const float* Wopt = (const float*)d_in[10];
    const float* bopt = (const float*)d_in[11];
    const float* Wb1  = (const float*)d_in[12];
    const float* bb1  = (const float*)d_in[13];
    const float* Wb2  = (const float*)d_in[14];
    const float* bb2  = (const float*)d_in[15];
    float* out = (float*)d_out;

    __half* pLin;
    float *pAct, *pDinv, *pAs, *pAd, *pEmb, *pWcsr, *pEv;
    int *pDeg, *pRp, *pLen, *pCur, *pCsr, *pCtr;
    cudaGetSymbolAddress((void**)&pLin,  g_lin);
    cudaGetSymbolAddress((void**)&pAct,  g_act);
    cudaGetSymbolAddress((void**)&pDeg,  g_deg);
    cudaGetSymbolAddress((void**)&pRp,   g_rowptr);
    cudaGetSymbolAddress((void**)&pLen,  g_len);
    cudaGetSymbolAddress((void**)&pCur,  g_cursor);
    cudaGetSymbolAddress((void**)&pCsr,  g_csr);
    cudaGetSymbolAddress((void**)&pWcsr, g_wcsr);
    cudaGetSymbolAddress((void**)&pEv,   g_ev);
    cudaGetSymbolAddress((void**)&pDinv, g_dinv);
    cudaGetSymbolAddress((void**)&pAs,   g_as);
    cudaGetSymbolAddress((void**)&pAd,   g_ad);
    cudaGetSymbolAddress((void**)&pEmb,  g_emb);
    cudaGetSymbolAddress((void**)&pCtr,  g_ctr);

    const int TB = 256;
    const int nBlkA = (NN + 7) / 8;                // warp per node
    const int nBlkG = (NN + 127) / 128;
    const int smemT = 128 * 68 * 4;                // 34816 (overlay dominates)

    static cudaStream_t s1 = nullptr;
    static cudaEvent_t ev0 = nullptr, ev1 = nullptr;
    static int attr_done = 0;
    if (!attr_done) {
        cudaFuncSetAttribute(k_gemm_t<64, true>,  cudaFuncAttributeMaxDynamicSharedMemorySize, smemT);
        cudaFuncSetAttribute(k_gemm_t<64, false>, cudaFuncAttributeMaxDynamicSharedMemorySize, smemT);
        cudaFuncSetAttribute(k_gemm_t<32, false>, cudaFuncAttributeMaxDynamicSharedMemorySize, smemT);
        cudaStreamCreateWithFlags(&s1, cudaStreamNonBlocking);
        cudaEventCreateWithFlags(&ev0, cudaEventDisableTiming);
        cudaEventCreateWithFlags(&ev1, cudaEventDisableTiming);
        attr_done = 1;
    }

    // ---- fork: CSR build on s1, overlapped with GEMM1 on stream 0 ----
    cudaEventRecord(ev0, 0);
    cudaStreamWaitEvent(s1, ev0, 0);
    k_deg_count<<<(EE + 1023) / 1024, TB, 0, s1>>>(dst, pDeg);
    k_rp<<<NB, TB, 0, s1>>>(pDeg, pRp, pCur, pLen, pDinv, pEmb, pCtr);
    k_csr_fill<<<(ET + 1023) / 1024, TB, 0, s1>>>(src, dst, pCur, pCsr, pDinv, pWcsr);
    cudaEventRecord(ev1, s1);

    // ---- GCN layer 1 ----
    k_gemm_t<32, false><<<nBlkG, TB, smemT>>>(x, W1, pLin, nullptr, nullptr, nullptr, nullptr, NN);
    cudaStreamWaitEvent(0, ev1, 0);   // join: aggs need CSR + weights
    k_gcn_agg<<<nBlkA, TB>>>(pLin, pRp, pLen, pCsr, pWcsr, b1, pAct);

    // ---- GAT layer (alpha fused into GEMM epilogue) ----
    k_gemm_t<64, true><<<nBlkG, TB, smemT>>>(pAct, W2, pLin, a_s, a_d, pAs, pAd, NN);
    k_gat_agg<<<nBlkA, TB>>>(pLin, pRp, pLen, pCsr, pAs, pAd, pEv, b2, pAct);

    // ---- GCN layer 3 ----
    k_gemm_t<64, false><<<nBlkG, TB, smemT>>>(pAct, W3, pLin, nullptr, nullptr, nullptr, nullptr, NN);
    k_gcn_agg<<<nBlkA, TB>>>(pLin, pRp, pLen, pCsr, pWcsr, b3, pAct);

    // ---- heads + embedding (finish fused via last-block ticket) ----
    k_heads<<<1184, TB>>>(pAct, Wopt, bopt, Wb1, bb1, Wb2, bb2, out, pEmb, pCtr + 2, NN);
}

// round 14
// speedup vs baseline: 1.3188x; 1.0529x over previous
#include <cuda_runtime.h>
#include <cuda_bf16.h>
#include <cuda_fp16.h>
#include <mma.h>
#include <math.h>

using namespace nvcuda;

#define NN 100000
#define EE 1250000
#define ET (NN + EE)          // edges + self loops
#define CC 10
#define NB 391                // ceil(NN/256)

// -------- scratch (no allocations allowed) --------
__device__ __half g_lin[NN * 64];    // fp16 features for gathers
__device__ __half g_act[NN * 64];    // fp16 aggregated activations
__device__ int   g_deg[NN];          // starts zero (BSS); re-zeroed by k_rp each launch
__device__ int   g_rowptr[NN];
__device__ int   g_len[NN];
__device__ int   g_cursor[NN];
__device__ int   g_csr[ET];
__device__ float g_wcsr[ET];         // per-slot GCN norm (written in csr_fill)
__device__ float g_ev[ET];           // per-slot GAT exp(logit)
__device__ float g_dinv[NN];
__device__ float g_as[NN];
__device__ float g_ad[NN];
__device__ float g_emb[64];
__device__ int   g_ctr[4];           // [0]=rp base, [1]=rp ticket, [2]=heads ticket

// ======== CSR build ========
__global__ void k_deg_count(const int* __restrict__ dst, int* deg) {
    int t0 = blockIdx.x * 1024 + threadIdx.x;
#pragma unroll
    for (int j = 0; j < 4; j++) {
        int i = t0 + j * 256;
        if (i < EE) atomicAdd(&deg[dst[i]], 1);
    }
}
__global__ void k_rp(int* __restrict__ deg, int* __restrict__ rp, int* __restrict__ cur,
                     int* __restrict__ len, float* __restrict__ dinv,
                     float* __restrict__ emb, int* __restrict__ ctr) {
    __shared__ int s[256];
    __shared__ int base;
    int t = threadIdx.x;
    int i = blockIdx.x * 256 + t;
    int v = (i < NN) ? (deg[i] + 1) : 0;       // +1 self loop
    s[t] = v;
    __syncthreads();
    for (int off = 1; off < 256; off <<= 1) {
        int u = (t >= off) ? s[t - off] : 0;
        __syncthreads();
        s[t] += u;
        __syncthreads();
    }
    if (t == 255) base = atomicAdd(&ctr[0], s[255]);
    __syncthreads();
    if (i < NN) {
        int ex = base + s[t] - v;
        rp[i] = ex;
        cur[i] = ex;
        len[i] = v;
        dinv[i] = rsqrtf((float)v);
        deg[i] = 0;                            // ready for next replay
    }
    if (blockIdx.x == 0 && t < 64) emb[t] = 0.f;
    __threadfence();
    if (t == 0) {
        int done = atomicAdd(&ctr[1], 1);
        if (done == gridDim.x - 1) { ctr[0] = 0; ctr[1] = 0; }
    }
}
__global__ void k_csr_fill(const int* __restrict__ src, const int* __restrict__ dst,
                           int* __restrict__ cur, int* __restrict__ csr,
                           const float* __restrict__ dinv, float* __restrict__ wcsr) {
    int t0 = blockIdx.x * 1024 + threadIdx.x;
#pragma unroll
    for (int j = 0; j < 4; j++) {
        int i = t0 + j * 256;
        if (i < ET) {
            int s, d;
            if (i < EE) { s = src[i]; d = dst[i]; } else { s = d = i - EE; }
            int pos = atomicAdd(&cur[d], 1);
            csr[pos] = s;
            wcsr[pos] = dinv[s] * dinv[d];
        }
    }
}

// ======== tensor-core GEMM: C_h[M,64] = A[M,K] @ W[K,64], fp16 in / fp32 accum ========
__device__ __forceinline__ uint2 cvt4(float4 v) {
    __half2 h0 = __float22half2_rn(make_float2(v.x, v.y));
    __half2 h1 = __float22half2_rn(make_float2(v.z, v.w));
    uint2 r;
    r.x = *(unsigned*)&h0;
    r.y = *(unsigned*)&h1;
    return r;
}

// AHALF: A is already fp16 (raw copy); else fp32 (convert).
template <int K, bool ALPHA, bool AHALF>
__global__ void k_gemm_t(const void* __restrict__ Avoid, const float* __restrict__ W,
                         __half* __restrict__ C,
                         const float* __restrict__ avs, const float* __restrict__ avd,
                         float* __restrict__ as_out, float* __restrict__ ad_out, int M) {
    extern __shared__ char smx[];
    const int AS = K + 8;                       // halves per As row
    __half* As = (__half*)smx;                  // 128*AS halves
    __half* Ws = As + 128 * AS;                 // K*72 halves
    float*  Os = (float*)smx;                   // OVERLAY (As/Ws dead after mainloop)
    int tid = threadIdx.x;
    int base = blockIdx.x * 128;

    // W: K*64 floats, float4-vectorized
    for (int idx = tid; idx < K * 16; idx += 256) {
        int r = idx >> 4, c4 = (idx & 15) * 4;
        float4 v = *(const float4*)&W[r * 64 + c4];
        *(uint2*)&Ws[r * 72 + c4] = cvt4(v);
    }
    if (AHALF) {
        const __half* Ah = (const __half*)Avoid;
        for (int idx = tid; idx < 128 * (K / 8); idx += 256) {
            int r = idx / (K / 8), c8 = (idx - r * (K / 8)) * 8;
            int row = base + r;
            uint4 v = (row < M) ? *(const uint4*)&Ah[row * K + c8]
                                : make_uint4(0u, 0u, 0u, 0u);
            *(uint4*)&As[r * AS + c8] = v;
        }
    } else {
        const float* Af = (const float*)Avoid;
        const int RQ = K / 4;
        for (int idx = tid; idx < 128 * RQ; idx += 256) {
            int r = idx / RQ, c4 = (idx - r * RQ) * 4;
            int row = base + r;
            float4 v = (row < M) ? *(const float4*)&Af[row * K + c4]
                                 : make_float4(0.f, 0.f, 0.f, 0.f);
            *(uint2*)&As[r * AS + c4] = cvt4(v);
        }
    }
    __syncthreads();

    int w = tid >> 5;
    wmma::fragment<wmma::matrix_a, 16, 16, 16, __half, wmma::row_major> fa;
    wmma::fragment<wmma::matrix_b, 16, 16, 16, __half, wmma::row_major> fb;
    wmma::fragment<wmma::accumulator, 16, 16, 16, float> fc[4];
#pragma unroll
    for (int j = 0; j < 4; j++) wmma::fill_fragment(fc[j], 0.f);
#pragma unroll
    for (int kk = 0; kk < K / 16; kk++) {
        wmma::load_matrix_sync(fa, As + w * 16 * AS + kk * 16, AS);
#pragma unroll
        for (int j = 0; j < 4; j++) {
            wmma::load_matrix_sync(fb, Ws + kk * 16 * 72 + j * 16, 72);
            wmma::mma_sync(fc[j], fa, fb, fc[j]);
        }
    }
    __syncthreads();                            // all reads of As/Ws complete before overlay
#pragma unroll
    for (int j = 0; j < 4; j++)
        wmma::store_matrix_sync(Os + w * 16 * 68 + j * 16, fc[j], 68, wmma::mem_row_major);
    __syncthreads();

    // epilogue: thread t -> row t>>1, 32-col half (t&1)
    int r = tid >> 1, ch = (tid & 1) * 32;
    int row = base + r;
    float f[32];
#pragma unroll
    for (int i = 0; i < 8; i++) {
        float4 v = *(float4*)&Os[r * 68 + ch + i * 4];
        f[i * 4] = v.x; f[i * 4 + 1] = v.y; f[i * 4 + 2] = v.z; f[i * 4 + 3] = v.w;
    }
    if (row < M) {
        __half2 hh[16];
#pragma unroll
        for (int i = 0; i < 16; i++)
            hh[i] = __float22half2_rn(make_float2(f[2 * i], f[2 * i + 1]));
#pragma unroll
        for (int i = 0; i < 4; i++)
            *(uint4*)&C[row * 64 + ch + i * 8] = ((uint4*)hh)[i];
    }
    if (ALPHA) {
        float sp = 0.f, dp = 0.f;
#pragma unroll
        for (int i = 0; i < 32; i++) {
            sp = fmaf(f[i], avs[ch + i], sp);
            dp = fmaf(f[i], avd[ch + i], dp);
        }
        sp += __shfl_xor_sync(0xffffffffu, sp, 1);
        dp += __shfl_xor_sync(0xffffffffu, dp, 1);
        if ((tid & 1) == 0 && row < M) { as_out[row] = sp; ad_out[row] = dp; }
    }
}

// ======== quarter-warp gather: lane q in group holds halves 8q..8q+7 ========
__device__ __forceinline__ void hacc8(const uint4* __restrict__ hp, int s, int q, float m,
                                      float acc[8]) {
    uint4 rv = hp[(unsigned)s * 8 + q];
    float2 f0 = __half22float2(*(__half2*)&rv.x);
    float2 f1 = __half22float2(*(__half2*)&rv.y);
    float2 f2 = __half22float2(*(__half2*)&rv.z);
    float2 f3 = __half22float2(*(__half2*)&rv.w);
    acc[0] = fmaf(f0.x, m, acc[0]); acc[1] = fmaf(f0.y, m, acc[1]);
    acc[2] = fmaf(f1.x, m, acc[2]); acc[3] = fmaf(f1.y, m, acc[3]);
    acc[4] = fmaf(f2.x, m, acc[4]); acc[5] = fmaf(f2.y, m, acc[5]);
    acc[6] = fmaf(f3.x, m, acc[6]); acc[7] = fmaf(f3.y, m, acc[7]);
}

// bias + relu + fp16 pack, 16B store per group lane
__device__ __forceinline__ void agg_epilogue(float acc[8], const float* __restrict__ b,
                                             __half* __restrict__ act, int node, int lane) {
#pragma unroll
    for (int j = 0; j < 8; j++) {
        acc[j] += __shfl_xor_sync(0xffffffffu, acc[j], 8);
        acc[j] += __shfl_xor_sync(0xffffffffu, acc[j], 16);
    }
    if (lane < 8) {
        int fi = lane * 8;
        float4 b0 = *(const float4*)&b[fi];
        float4 b1 = *(const float4*)&b[fi + 4];
        __half2 hh[4];
        hh[0] = __float22half2_rn(make_float2(fmaxf(acc[0] + b0.x, 0.f), fmaxf(acc[1] + b0.y, 0.f)));
        hh[1] = __float22half2_rn(make_float2(fmaxf(acc[2] + b0.z, 0.f), fmaxf(acc[3] + b0.w, 0.f)));
        hh[2] = __float22half2_rn(make_float2(fmaxf(acc[4] + b1.x, 0.f), fmaxf(acc[5] + b1.y, 0.f)));
        hh[3] = __float22half2_rn(make_float2(fmaxf(acc[6] + b1.z, 0.f), fmaxf(acc[7] + b1.w, 0.f)));
        *(uint4*)&act[node * 64 + fi] = *(uint4*)hh;
    }
}

// ======== GCN aggregation: warp per node, quarter-warp per edge ========
__global__ void k_gcn_agg(const __half* __restrict__ h, const int* __restrict__ rp,
                          const int* __restrict__ lenv, const int* __restrict__ csr,
                          const float* __restrict__ wcsr,
                          const float* __restrict__ b, __half* __restrict__ act) {
    int node = blockIdx.x * 8 + (threadIdx.x >> 5);
    if (node >= NN) return;
    int lane = threadIdx.x & 31;
    int g = lane >> 3;          // quarter id
    int q = lane & 7;           // lane in quarter
    const uint4* hp = (const uint4*)h;
    int e = rp[node];
    int end = e + lenv[node];
    float acc[8];
#pragma unroll
    for (int j = 0; j < 8; j++) acc[j] = 0.f;
    for (; e + 8 <= end; e += 8) {
        int eA = e + g, eB = e + 4 + g;
        int sA = csr[eA], sB = csr[eB];
        float mA = wcsr[eA], mB = wcsr[eB];
        hacc8(hp, sA, q, mA, acc);
        hacc8(hp, sB, q, mB, acc);
    }
    for (; e < end; e += 4) {
        int ee = e + g;
        if (ee < end) hacc8(hp, csr[ee], q, wcsr[ee], acc);
    }
    agg_epilogue(acc, b, act, node, lane);
}

__device__ __forceinline__ float lrelu(float v) { return v >= 0.f ? v : 0.2f * v; }

// ======== fused GAT aggregation: no-max softmax + exp spill + weighted gather ========
__global__ void k_gat_agg(const __half* __restrict__ h, const int* __restrict__ rp,
                          const int* __restrict__ lenv, const int* __restrict__ csr,
                          const float* __restrict__ as_, const float* __restrict__ ad_,
                          float* __restrict__ ev,
                          const float* __restrict__ b, __half* __restrict__ act) {
    int node = blockIdx.x * 8 + (threadIdx.x >> 5);
    if (node >= NN) return;
    int lane = threadIdx.x & 31;
    int g = lane >> 3;
    int q = lane & 7;
    const uint4* hp = (const uint4*)h;
    int begin = rp[node];
    int end = begin + lenv[node];
    float adv = ad_[node];

    float sum = 0.f;
    for (int e = begin + lane; e < end; e += 32) {
        float p = __expf(lrelu(as_[csr[e]] + adv));
        ev[e] = p;
        sum += p;
    }
#pragma unroll
    for (int o = 16; o; o >>= 1) sum += __shfl_xor_sync(0xffffffffu, sum, o);
    float inv = 1.f / sum;

    float acc[8];
#pragma unroll
    for (int j = 0; j < 8; j++) acc[j] = 0.f;
    int e = begin;
    for (; e + 8 <= end; e += 8) {
        int eA = e + g, eB = e + 4 + g;
        int sA = csr[eA], sB = csr[eB];
        float aA = ev[eA] * inv;
        float aB = ev[eB] * inv;
        hacc8(hp, sA, q, aA, acc);
        hacc8(hp, sB, q, aB, acc);
    }
    for (; e < end; e += 4) {
        int ee = e + g;
        if (ee < end) hacc8(hp, csr[ee], q, ev[ee] * inv, acc);
    }
    agg_epilogue(acc, b, act, node, lane);
}

// ======== heads + graph embedding (fp16 input; block-reduced atomics) ========
__global__ void k_heads(const __half* __restrict__ h,
                        const float* __restrict__ Wopt, const float* __restrict__ bopt,
                        const float* __restrict__ Wb1, const float* __restrict__ bb1,
                        const float* __restrict__ Wb2, const float* __restrict__ bb2,
                        float* __restrict__ out, float* __restrict__ emb,
                        int* __restrict__ ticket, int n) {
    __shared__ float sWopt[640], sbopt[10], sbb1[32], sWb2[32];
    __shared__ float hrow[8][64];
    __shared__ float semb[64];
    __shared__ int islast;
    int tid = threadIdx.x;
    for (int i = tid; i < 640; i += 256) sWopt[i] = Wopt[i];
    if (tid < 10) sbopt[tid] = bopt[tid];
    if (tid < 32) { sbb1[tid] = bb1[tid]; sWb2[tid] = Wb2[tid]; }
    if (tid < 64) semb[tid] = 0.f;
    __syncthreads();
    float bb2v = bb2[0];
    int warp = tid >> 5, lane = tid & 31;
    float wb1r[64];
#pragma unroll
    for (int k = 0; k < 64; k++) wb1r[k] = Wb1[k * 32 + lane];
    float p0 = 0.f, p1 = 0.f;
    bool opt_lane = lane < CC;
    for (int node = blockIdx.x * 8 + warp; node < n; node += gridDim.x * 8) {
        float2 hv = __half22float2(*(const __half2*)&h[node * 64 + lane * 2]);
        hrow[warp][lane * 2] = hv.x;
        hrow[warp][lane * 2 + 1] = hv.y;
        p0 += hv.x; p1 += hv.y;
        __syncwarp();
        float t = sbb1[lane];
        float acc = opt_lane ? sbopt[lane] : 0.f;
#pragma unroll
        for (int k = 0; k < 64; k++) {
            float hk = hrow[warp][k];
            t = fmaf(hk, wb1r[k], t);
            if (opt_lane) acc = fmaf(hk, sWopt[k * CC + lane], acc);
        }
        if (opt_lane) out[node * CC + lane] = acc;
        t = fmaxf(t, 0.f) * sWb2[lane];
#pragma unroll
        for (int o = 16; o; o >>= 1) t += __shfl_down_sync(0xffffffffu, t, o);
        if (lane == 0) out[NN * CC + node] = 1.f / (1.f + __expf(-(t + bb2v)));
        __syncwarp();
    }
    atomicAdd(&semb[lane * 2], p0);
    atomicAdd(&semb[lane * 2 + 1], p1);
    __syncthreads();
    if (tid < 64) atomicAdd(&emb[tid], semb[tid]);
    __threadfence();
    if (tid == 0) {
        int done = atomicAdd(ticket, 1);
        islast = (done == gridDim.x - 1);
    }
    __syncthreads();
    if (islast) {
        if (tid < 64) out[NN * CC + NN + tid] = emb[tid] * (1.0f / NN);
        if (tid == 0) *ticket = 0;
    }
}

// ======== launch ========
extern "C" void kernel_launch(void* const* d_in, const int* in_sizes, int n_in,
                              void* d_out, int out_size) {
    const float* x    = (const float*)d_in[0];
    const int*   ei   = (const int*)d_in[1];
    const int*   src  = ei;
    const int*   dst  = ei + EE;
    const float* W1   = (const float*)d_in[2];
    const float* b1   = (const float*)d_in[3];
    const float* W2   = (const float*)d_in[4];
    const float* a_s  = (const float*)d_in[5];
    const float* a_d  = (const float*)d_in[6];
    const float* b2   = (const float*)d_in[7];
    const float* W3   = (const float*)d_in[8];
    const float* b3   = (const float*)d_in[9];
    const float* Wopt = (const float*)d_in[10];
    const float* bopt = (const float*)d_in[11];
    const float* Wb1  = (const float*)d_in[12];
    const float* bb1  = (const float*)d_in[13];
    const float* Wb2  = (const float*)d_in[14];
    const float* bb2  = (const float*)d_in[15];
    float* out = (float*)d_out;

    __half *pLin, *pAct;
    float *pDinv, *pAs, *pAd, *pEmb, *pWcsr, *pEv;
    int *pDeg, *pRp, *pLen, *pCur, *pCsr, *pCtr;
    cudaGetSymbolAddress((void**)&pLin,  g_lin);
    cudaGetSymbolAddress((void**)&pAct,  g_act);
    cudaGetSymbolAddress((void**)&pDeg,  g_deg);
    cudaGetSymbolAddress((void**)&pRp,   g_rowptr);
    cudaGetSymbolAddress((void**)&pLen,  g_len);
    cudaGetSymbolAddress((void**)&pCur,  g_cursor);
    cudaGetSymbolAddress((void**)&pCsr,  g_csr);
    cudaGetSymbolAddress((void**)&pWcsr, g_wcsr);
    cudaGetSymbolAddress((void**)&pEv,   g_ev);
    cudaGetSymbolAddress((void**)&pDinv, g_dinv);
    cudaGetSymbolAddress((void**)&pAs,   g_as);
    cudaGetSymbolAddress((void**)&pAd,   g_ad);
    cudaGetSymbolAddress((void**)&pEmb,  g_emb);
    cudaGetSymbolAddress((void**)&pCtr,  g_ctr);

    const int TB = 256;
    const int nBlkA = (NN + 7) / 8;                // warp per node
    const int nBlkG = (NN + 127) / 128;
    const int smemT = 128 * 68 * 4;                // 34816 (overlay dominates)

    static cudaStream_t s1 = nullptr;
    static cudaEvent_t ev0 = nullptr, ev1 = nullptr;
    static int attr_done = 0;
    if (!attr_done) {
        cudaFuncSetAttribute((const void*)k_gemm_t<64, true, true>,
                             cudaFuncAttributeMaxDynamicSharedMemorySize, smemT);
        cudaFuncSetAttribute((const void*)k_gemm_t<64, false, true>,
                             cudaFuncAttributeMaxDynamicSharedMemorySize, smemT);
        cudaFuncSetAttribute((const void*)k_gemm_t<32, false, false>,
                             cudaFuncAttributeMaxDynamicSharedMemorySize, smemT);
        cudaStreamCreateWithFlags(&s1, cudaStreamNonBlocking);
        cudaEventCreateWithFlags(&ev0, cudaEventDisableTiming);
        cudaEventCreateWithFlags(&ev1, cudaEventDisableTiming);
        attr_done = 1;
    }

    // ---- fork: CSR build on s1, overlapped with GEMM1 on stream 0 ----
    cudaEventRecord(ev0, 0);
    cudaStreamWaitEvent(s1, ev0, 0);
    k_deg_count<<<(EE + 1023) / 1024, TB, 0, s1>>>(dst, pDeg);
    k_rp<<<NB, TB, 0, s1>>>(pDeg, pRp, pCur, pLen, pDinv, pEmb, pCtr);
    k_csr_fill<<<(ET + 1023) / 1024, TB, 0, s1>>>(src, dst, pCur, pCsr, pDinv, pWcsr);
    cudaEventRecord(ev1, s1);

    // ---- GCN layer 1 ----
    k_gemm_t<32, false, false><<<nBlkG, TB, smemT>>>(x, W1, pLin, nullptr, nullptr, nullptr, nullptr, NN);
    cudaStreamWaitEvent(0, ev1, 0);   // join: aggs need CSR + weights
    k_gcn_agg<<<nBlkA, TB>>>(pLin, pRp, pLen, pCsr, pWcsr, b1, pAct);

    // ---- GAT layer (alpha fused into GEMM epilogue) ----
    k_gemm_t<64, true, true><<<nBlkG, TB, smemT>>>(pAct, W2, pLin, a_s, a_d, pAs, pAd, NN);
    k_gat_agg<<<nBlkA, TB>>>(pLin, pRp, pLen, pCsr, pAs, pAd, pEv, b2, pAct);

    // ---- GCN layer 3 ----
    k_gemm_t<64, false, true><<<nBlkG, TB, smemT>>>(pAct, W3, pLin, nullptr, nullptr, nullptr, nullptr, NN);
    k_gcn_agg<<<nBlkA, TB>>>(pLin, pRp, pLen, pCsr, pWcsr, b3, pAct);

    // ---- heads + embedding (finish fused via last-block ticket) ----
    k_heads<<<1184, TB>>>(pAct, Wopt, bopt, Wb1, bb1, Wb2, bb2, out, pEmb, pCtr + 2, NN);
}